// round 14
// baseline (speedup 1.0000x reference)
#include <cuda_runtime.h>
#include <cuda_fp16.h>
#include <cstdint>

#define BB 512
#define HH 1024
#define GG 4096
#define TT 82
#define DD 129
#define STEPS 100
#define OUTN 128
#define XS2 4096          // state row: h0_e(0) h0_o(1024) h1_e(2048) h1_o(3072)
#define XALLW 136
#define KE0 1216
#define K2048 2048

// ===================== device scratch =====================
__device__ float  g_X  [BB * XS2];      // fp32 state
__device__ __half g_Xh [BB * XS2];      // fp16 mirror
__device__ float  g_C0 [BB * HH];
__device__ float  g_C1 [BB * HH];
__device__ __half g_Xall[TT * BB * XALLW];   // x pre-converted, 136-padded
__device__ __half g_H1h [STEPS * BB * HH];   // decoder h1 history (fp16) for batched fc
__device__ __half g_We0[GG * KE0];      // [Wih0(129)|z(7)|Whh0(1024)|z], gate-interleaved
__device__ __half g_We1[GG * K2048];    // [Wih1|Whh1]
__device__ __half g_Wd0[GG * K2048];    // [Whh0 | M0=Wih0@fcW]
__device__ __half g_Wd1[GG * K2048];    // [Wih1|Whh1] (dec)
__device__ __half g_fcWh[OUTN * HH];    // fc weights fp16 (plain order)
__device__ float  g_bias[5 * GG];       // e0,e1,d0_plain,d1,d0_folded

__device__ __forceinline__ uint32_t smem_u32(const void* p) {
    uint32_t a;
    asm("{ .reg .u64 t; cvta.to.shared.u64 t, %1; cvt.u32.u64 %0, t; }" : "=r"(a) : "l"(p));
    return a;
}
__device__ __forceinline__ void cpa16(uint32_t s, const void* g) {
    asm volatile("cp.async.cg.shared.global [%0], [%1], 16;" :: "r"(s), "l"(g));
}
__device__ __forceinline__ void ldsm4(uint32_t (&d)[4], uint32_t addr) {
    asm volatile("ldmatrix.sync.aligned.m8n8.x4.shared.b16 {%0,%1,%2,%3}, [%4];"
                 : "=r"(d[0]), "=r"(d[1]), "=r"(d[2]), "=r"(d[3]) : "r"(addr));
}
__device__ __forceinline__ void mma16816(float (&d)[4], const uint32_t (&a)[4],
                                         uint32_t b0, uint32_t b1) {
    asm volatile("mma.sync.aligned.m16n8k16.row.col.f32.f16.f16.f32 "
                 "{%0,%1,%2,%3},{%4,%5,%6,%7},{%8,%9},{%0,%1,%2,%3};"
                 : "+f"(d[0]), "+f"(d[1]), "+f"(d[2]), "+f"(d[3])
                 : "r"(a[0]), "r"(a[1]), "r"(a[2]), "r"(a[3]), "r"(b0), "r"(b1));
}

// ===================== setup kernels (5 launches) =====================
__global__ void setup_zero() {
    const int n1 = BB * XS2;
    const int n2 = BB * XS2 / 2;
    const int n3 = BB * HH;
    const int n4 = BB * HH;
    const int total = n1 + n2 + n3 + n4;
    for (int i = blockIdx.x * blockDim.x + threadIdx.x; i < total; i += gridDim.x * blockDim.x) {
        if (i < n1) g_X[i] = 0.f;
        else if (i < n1 + n2) ((uint32_t*)g_Xh)[i - n1] = 0u;
        else if (i < n1 + n2 + n3) g_C0[i - n1 - n2] = 0.f;
        else g_C1[i - n1 - n2 - n3] = 0.f;
    }
}

__global__ void setup_weights(const float* __restrict__ eWih0, const float* __restrict__ eWhh0,
                              const float* __restrict__ eWih1, const float* __restrict__ eWhh1,
                              const float* __restrict__ dWhh0,
                              const float* __restrict__ dWih1, const float* __restrict__ dWhh1) {
    const long S0 = (long)GG * KE0;
    const long S1 = (long)GG * K2048;
    const long S2 = (long)GG * K2048;
    const long S3 = (long)GG * 1024;
    const long total = S0 + S1 + S2 + S3;
    for (long i = blockIdx.x * (long)blockDim.x + threadIdx.x; i < total;
         i += (long)gridDim.x * blockDim.x) {
        if (i < S0) {
            int nd = (int)(i / KE0), k = (int)(i % KE0);
            int n = (nd & 3) * HH + (nd >> 2);
            float v = 0.f;
            if (k < 129) v = eWih0[(size_t)n * 129 + k];
            else if (k >= 136 && k < 1160) v = eWhh0[(size_t)n * 1024 + (k - 136)];
            g_We0[i] = __float2half(v);
        } else if (i < S0 + S1) {
            long j = i - S0;
            int nd = (int)(j / K2048), k = (int)(j % K2048);
            int n = (nd & 3) * HH + (nd >> 2);
            float v = (k < 1024) ? eWih1[(size_t)n * 1024 + k]
                                 : eWhh1[(size_t)n * 1024 + (k - 1024)];
            g_We1[j] = __float2half(v);
        } else if (i < S0 + S1 + S2) {
            long j = i - S0 - S1;
            int nd = (int)(j / K2048), k = (int)(j % K2048);
            int n = (nd & 3) * HH + (nd >> 2);
            float v = (k < 1024) ? dWih1[(size_t)n * 1024 + k]
                                 : dWhh1[(size_t)n * 1024 + (k - 1024)];
            g_Wd1[j] = __float2half(v);
        } else {
            long j = i - S0 - S1 - S2;
            int nd = (int)(j / 1024), k = (int)(j % 1024);
            int n = (nd & 3) * HH + (nd >> 2);
            g_Wd0[(size_t)nd * K2048 + k] = __float2half(dWhh0[(size_t)n * 1024 + k]);
        }
    }
}

// Wd0[:, 1024:2048] = M0 = Wih0 @ fcW  (fc folded into dec L0)
__global__ void setup_M0(const float* __restrict__ dWih0, const float* __restrict__ fcW) {
    __shared__ float sW[32][128];
    __shared__ float sF[128][64];
    const int nd0 = blockIdx.x * 32;
    const int k0  = blockIdx.y * 64;
    const int tid = threadIdx.x;
    for (int i = tid; i < 32 * 128; i += 256) {
        int r = i >> 7, o = i & 127;
        int nd = nd0 + r, n = (nd & 3) * HH + (nd >> 2);
        sW[r][o] = dWih0[(size_t)n * 128 + o];
    }
    for (int i = tid; i < 128 * 64; i += 256) {
        int o = i >> 6, kk = i & 63;
        sF[o][kk] = fcW[(size_t)o * HH + k0 + kk];
    }
    __syncthreads();
    for (int i = tid; i < 32 * 64; i += 256) {
        int r = i >> 6, kk = i & 63;
        float acc = 0.f;
#pragma unroll 16
        for (int o = 0; o < 128; o++) acc += sW[r][o] * sF[o][kk];
        g_Wd0[(size_t)(nd0 + r) * K2048 + 1024 + k0 + kk] = __float2half(acc);
    }
}

__global__ void setup_bias(const float* eb0a, const float* eb0b,
                           const float* eb1a, const float* eb1b,
                           const float* db0a, const float* db0b,
                           const float* db1a, const float* db1b,
                           const float* __restrict__ dWih0, const float* __restrict__ fcb) {
    int nd = blockIdx.x * blockDim.x + threadIdx.x;
    if (nd >= GG) return;
    int n = (nd & 3) * HH + (nd >> 2);
    g_bias[0 * GG + nd] = eb0a[n] + eb0b[n];
    g_bias[1 * GG + nd] = eb1a[n] + eb1b[n];
    float d0 = db0a[n] + db0b[n];
    g_bias[2 * GG + nd] = d0;
    g_bias[3 * GG + nd] = db1a[n] + db1b[n];
    float acc = 0.f;
#pragma unroll 16
    for (int o = 0; o < 128; o++) acc += dWih0[(size_t)n * 128 + o] * fcb[o];
    g_bias[4 * GG + nd] = d0 + acc;
}

// fcW -> fp16 (plain order) + x -> g_Xall (136-padded fp16)
__global__ void setup_misc(const float* __restrict__ fcW, const float* __restrict__ x) {
    const int t1 = OUTN * HH;
    const int t2 = TT * BB * XALLW;
    for (int i = blockIdx.x * blockDim.x + threadIdx.x; i < t1 + t2;
         i += gridDim.x * blockDim.x) {
        if (i < t1) {
            g_fcWh[i] = __float2half(fcW[i]);
        } else {
            int j = i - t1;
            int tt = j / (BB * XALLW);
            int r = j % (BB * XALLW);
            int b = r / XALLW, k = r % XALLW;
            float v = (k < DD) ? x[(size_t)b * (TT * DD) + tt * DD + k] : 0.f;
            g_Xall[j] = __float2half(v);
        }
    }
}

// ===================== fused GEMM + LSTM cell =====================
#define TBYTES 16384
#define STAGE_B (2 * TBYTES)      // 32 KB
#define SMEM_G  (4 * STAGE_B)     // 128 KB: 4-stage, single sync per chunk
#define SMEM_F  (3 * STAGE_B)     // 96 KB: fc_batch 3-stage

#define GEMM_PROLOGUE()                                                            \
    const uint32_t sb = smem_u32(smem);                                            \
    const int tid = threadIdx.x;                                                   \
    const int l = tid & 31;                                                        \
    const int wid = tid >> 5;                                                      \
    const int warp_m = wid >> 2;                                                   \
    const int warp_n = wid & 3;                                                    \
    const int rowL = tid >> 3;                                                     \
    const int colL = tid & 7;                                                      \
    const uint32_t swL = (uint32_t)(colL ^ (rowL & 7)) * 16;                       \
    uint32_t arow[4], ar7[4];                                                      \
    _Pragma("unroll")                                                              \
    for (int wm = 0; wm < 4; wm++) {                                               \
        const uint32_t r = warp_m * 64 + wm * 16 + (l & 15);                       \
        arow[wm] = r * 128; ar7[wm] = r & 7;                                       \
    }                                                                              \
    uint32_t brow[2], br7[2];                                                      \
    _Pragma("unroll")                                                              \
    for (int p = 0; p < 2; p++) {                                                  \
        const uint32_t r = warp_n * 32 + p * 16 + ((l >> 4) << 3) + (l & 7);       \
        brow[p] = r * 128; br7[p] = r & 7;                                         \
    }                                                                              \
    const uint32_t acsel = (uint32_t)(l >> 4);                                     \
    const uint32_t bcsel = (uint32_t)((l >> 3) & 1);                               \
    uint32_t AH2[2][4][4], BH2[2][2][4];                                           \
    float acc[4][4][4];                                                            \
    _Pragma("unroll")                                                              \
    for (int i = 0; i < 4; i++)                                                    \
        _Pragma("unroll")                                                          \
        for (int j = 0; j < 4; j++)                                                \
            _Pragma("unroll")                                                      \
            for (int q = 0; q < 4; q++) acc[i][j][q] = 0.f;

// load A/B fragments for k-slice ks into register buffer buf
#define LD_FRAGS(buf, st, ks)                                                      \
    do {                                                                           \
        const uint32_t cA_ = (uint32_t)(2 * (ks)) + acsel;                         \
        _Pragma("unroll")                                                          \
        for (int wm = 0; wm < 4; wm++)                                             \
            ldsm4(AH2[buf][wm], (st) + arow[wm] + ((cA_ ^ ar7[wm]) << 4));         \
        const uint32_t cB_ = (uint32_t)(2 * (ks)) + bcsel;                         \
        _Pragma("unroll")                                                          \
        for (int p = 0; p < 2; p++)                                                \
            ldsm4(BH2[buf][p], (st) + TBYTES + brow[p] + ((cB_ ^ br7[p]) << 4));   \
    } while (0)

#define MMA_FRAGS(buf)                                                             \
    do {                                                                           \
        _Pragma("unroll")                                                          \
        for (int wm = 0; wm < 4; wm++) {                                           \
            _Pragma("unroll")                                                      \
            for (int wn = 0; wn < 4; wn++) {                                       \
                const int p_ = wn >> 1, h_ = (wn & 1) << 1;                        \
                mma16816(acc[wm][wn], AH2[buf][wm],                                \
                         BH2[buf][p_][h_], BH2[buf][p_][h_ + 1]);                  \
            }                                                                      \
        }                                                                          \
    } while (0)

// register-double-buffered chunk compute: load ks+1 while issuing MMAs of ks
#define GEMM_COMPUTE_CHUNK(st)                                                     \
    do {                                                                           \
        LD_FRAGS(0, st, 0);                                                        \
        _Pragma("unroll")                                                          \
        for (int ks = 0; ks < 4; ks++) {                                           \
            if (ks < 3) LD_FRAGS((ks + 1) & 1, st, ks + 1);                        \
            MMA_FRAGS(ks & 1);                                                     \
        }                                                                          \
    } while (0)

// 4-stage, ONE __syncthreads per chunk (ring-safe: top sync of kc orders all
// compute of kc-1 before prefetch into stage (kc+3)&3 == (kc-1)&3).
#define GEMM_MAINLOOP4(LOADCHUNK)                                                  \
    LOADCHUNK(0, 0);                                                               \
    LOADCHUNK(1, 1);                                                               \
    LOADCHUNK(2, 2);                                                               \
    for (int kc = 0; kc < nch; kc++) {                                             \
        if (kc + 2 < nch) { asm volatile("cp.async.wait_group 2;"); }              \
        else if (kc + 1 < nch) { asm volatile("cp.async.wait_group 1;"); }         \
        else { asm volatile("cp.async.wait_group 0;"); }                           \
        __syncthreads();                                                           \
        if (kc + 3 < nch) LOADCHUNK((kc + 3) & 3, kc + 3);                         \
        const uint32_t st = sb + (uint32_t)(kc & 3) * STAGE_B;                     \
        GEMM_COMPUTE_CHUNK(st);                                                    \
    }                                                                              \
    __syncthreads();

#define GEMM_ACC_TO_SMEM(biasptr)                                                  \
    float* cs = (float*)smem;                                                      \
    _Pragma("unroll")                                                              \
    for (int wn = 0; wn < 4; wn++) {                                               \
        const int cl = warp_n * 32 + wn * 8 + (l & 3) * 2;                         \
        const float2 bv = *(const float2*)((biasptr) + cl);                        \
        _Pragma("unroll")                                                          \
        for (int wm = 0; wm < 4; wm++) {                                           \
            const int rl = warp_m * 64 + wm * 16 + (l >> 2);                       \
            cs[rl * 132 + cl]           = acc[wm][wn][0] + bv.x;                   \
            cs[rl * 132 + cl + 1]       = acc[wm][wn][1] + bv.y;                   \
            cs[(rl + 8) * 132 + cl]     = acc[wm][wn][2] + bv.x;                   \
            cs[(rl + 8) * 132 + cl + 1] = acc[wm][wn][3] + bv.y;                   \
        }                                                                          \
    }                                                                              \
    __syncthreads();

__global__ __launch_bounds__(256, 1)
void gemm_cell(const __half* __restrict__ A1, int ld1,
               const __half* __restrict__ A2, int ld2, int bnd,
               const __half* __restrict__ W, int ldw,
               const float* __restrict__ bias,
               float* __restrict__ Cc,
               const int* __restrict__ lengths, int t, int msk,
               int hW, int hR,
               __half* __restrict__ hist,       // decL1: h1 history slice, else null
               int K) {
    extern __shared__ char smem[];
    const int m0 = (int)blockIdx.y * 128;
    const int n0 = (int)blockIdx.x * 128;

    GEMM_PROLOGUE();

    const size_t ld1B = (size_t)ld1 * 2, ld2B = (size_t)ld2 * 2;
    const size_t ldwB = (size_t)ldw * 2;
    const char* pA1 = (const char*)A1 + (size_t)(m0 + rowL) * ld1B;
    const char* pA2 = (const char*)A2 + (size_t)(m0 + rowL) * ld2B;
    const char* pW  = (const char*)W  + (size_t)(n0 + rowL) * ldwB;
    const int nch = K >> 6;

#define LOADCHUNK_C(s, kc) do {                                                    \
    const uint32_t st_ = sb + (uint32_t)(s) * STAGE_B;                             \
    const int gcol_ = (kc) * 8 + colL;                                             \
    const char* ap_; size_t astep_;                                                \
    if (gcol_ < bnd) { ap_ = pA1 + (size_t)gcol_ * 16; astep_ = ld1B * 32; }       \
    else { ap_ = pA2 + (size_t)(gcol_ - bnd) * 16; astep_ = ld2B * 32; }           \
    const char* wp_ = pW + (size_t)gcol_ * 16;                                     \
    _Pragma("unroll")                                                              \
    for (int it = 0; it < 4; it++) {                                               \
        const uint32_t so_ = (uint32_t)(rowL + 32 * it) * 128 + swL;               \
        cpa16(st_ + so_, ap_ + (size_t)it * astep_);                               \
        cpa16(st_ + TBYTES + so_, wp_ + (size_t)(32 * it) * ldwB);                 \
    }                                                                              \
    asm volatile("cp.async.commit_group;");                                        \
} while (0)

    GEMM_MAINLOOP4(LOADCHUNK_C);
    GEMM_ACC_TO_SMEM(bias + n0);

    // ---- LSTM cell: 128 batch x 32 channels ----
    const int ch0 = n0 >> 2;
#pragma unroll
    for (int it = 0; it < 16; it++) {
        const int idx = it * 256 + tid;
        const int bl = idx >> 5;
        const int jl = idx & 31;
        const float4 v = *(const float4*)&cs[bl * 132 + 4 * jl];
        const int b = m0 + bl;
        const int j = ch0 + jl;
        const float ig = 1.f / (1.f + __expf(-v.x));
        const float fg = 1.f / (1.f + __expf(-v.y));
        const float gg = tanhf(v.z);
        const float og = 1.f / (1.f + __expf(-v.w));
        const size_t cidx = (size_t)b * HH + j;
        const size_t rowX = (size_t)b * XS2;
        const float cold = Cc[cidx];
        float cn = fg * cold + ig * gg;
        float hn = og * tanhf(cn);
        if (msk && t >= lengths[b]) {
            cn = cold;
            hn = g_X[rowX + hR + j];
        }
        Cc[cidx] = cn;
        g_X[rowX + hW + j] = hn;
        const __half hh = __float2half(hn);
        g_Xh[rowX + hW + j] = hh;
        if (hist) hist[(size_t)b * HH + j] = hh;
    }
}

// ===================== batched fc: out = H1hist @ fcW^T + fcb (one launch) =====================
__global__ __launch_bounds__(256, 1)
void fc_batch(const float* __restrict__ fcb, float* __restrict__ out) {
    extern __shared__ char smem[];
    const int m0 = (int)blockIdx.x * 128;     // m = t*BB + b, M = STEPS*BB = 51200

    GEMM_PROLOGUE();

    const size_t ldaB = (size_t)HH * 2;
    const char* pA = (const char*)g_H1h + (size_t)(m0 + rowL) * ldaB + colL * 16;
    const char* pW = (const char*)g_fcWh + (size_t)rowL * ldaB + colL * 16;
    const int nch = HH >> 6;   // 16

#define LOADCHUNK_F(s, kc) do {                                                    \
    const uint32_t st_ = sb + (uint32_t)(s) * STAGE_B;                             \
    const size_t ko_ = (size_t)(kc) * 128;                                         \
    _Pragma("unroll")                                                              \
    for (int it = 0; it < 4; it++) {                                               \
        const uint32_t so_ = (uint32_t)(rowL + 32 * it) * 128 + swL;               \
        cpa16(st_ + so_, pA + ko_ + (size_t)(32 * it) * ldaB);                     \
        cpa16(st_ + TBYTES + so_, pW + ko_ + (size_t)(32 * it) * ldaB);            \
    }                                                                              \
    asm volatile("cp.async.commit_group;");                                        \
} while (0)

    // 3-stage mainloop for fc_batch
    LOADCHUNK_F(0, 0);
    LOADCHUNK_F(1, 1);
    for (int kc = 0; kc < nch; kc++) {
        if (kc + 1 < nch) { asm volatile("cp.async.wait_group 1;"); }
        else { asm volatile("cp.async.wait_group 0;"); }
        __syncthreads();
        if (kc + 2 < nch) { const int s_ = (kc + 2) % 3; LOADCHUNK_F(s_, kc + 2); }
        const uint32_t st = sb + (uint32_t)(kc % 3) * STAGE_B;
        GEMM_COMPUTE_CHUNK(st);
        __syncthreads();
    }

    GEMM_ACC_TO_SMEM(fcb);

    // store: m = t*BB + b  ->  out[(b*STEPS + t)*OUTN + n]
#pragma unroll
    for (int it = 0; it < 16; it++) {
        const int idx = it * 256 + tid;
        const int bl = idx >> 5;
        const int jl = idx & 31;
        const int m = m0 + bl;
        const int b = m & (BB - 1);
        const int tt = m >> 9;
        const float4 v = *(const float4*)&cs[bl * 132 + 4 * jl];
        *(float4*)&out[((size_t)b * STEPS + tt) * OUTN + 4 * jl] = v;
    }
}

// ===================== host =====================
extern "C" void kernel_launch(void* const* d_in, const int* in_sizes, int n_in,
                              void* d_out, int out_size) {
    const float* x     = (const float*)d_in[0];
    const int*   lens  = (const int*)  d_in[1];
    const float* eWih0 = (const float*)d_in[2];
    const float* eWhh0 = (const float*)d_in[3];
    const float* ebih0 = (const float*)d_in[4];
    const float* ebhh0 = (const float*)d_in[5];
    const float* eWih1 = (const float*)d_in[6];
    const float* eWhh1 = (const float*)d_in[7];
    const float* ebih1 = (const float*)d_in[8];
    const float* ebhh1 = (const float*)d_in[9];
    const float* dWih0 = (const float*)d_in[10];
    const float* dWhh0 = (const float*)d_in[11];
    const float* dbih0 = (const float*)d_in[12];
    const float* dbhh0 = (const float*)d_in[13];
    const float* dWih1 = (const float*)d_in[14];
    const float* dWhh1 = (const float*)d_in[15];
    const float* dbih1 = (const float*)d_in[16];
    const float* dbhh1 = (const float*)d_in[17];
    const float* fcW   = (const float*)d_in[18];
    const float* fcb   = (const float*)d_in[19];
    float* out = (float*)d_out;

    float *Bias, *C0, *C1;
    __half *Xh, *Xall, *We0, *We1, *Wd0, *Wd1, *H1h;
    cudaGetSymbolAddress((void**)&C0,   g_C0);
    cudaGetSymbolAddress((void**)&C1,   g_C1);
    cudaGetSymbolAddress((void**)&Bias, g_bias);
    cudaGetSymbolAddress((void**)&Xh,   g_Xh);
    cudaGetSymbolAddress((void**)&Xall, g_Xall);
    cudaGetSymbolAddress((void**)&We0,  g_We0);
    cudaGetSymbolAddress((void**)&We1,  g_We1);
    cudaGetSymbolAddress((void**)&Wd0,  g_Wd0);
    cudaGetSymbolAddress((void**)&Wd1,  g_Wd1);
    cudaGetSymbolAddress((void**)&H1h,  g_H1h);

    cudaFuncSetAttribute(gemm_cell, cudaFuncAttributeMaxDynamicSharedMemorySize, SMEM_G);
    cudaFuncSetAttribute(fc_batch,  cudaFuncAttributeMaxDynamicSharedMemorySize, SMEM_F);

    // ---- setup: 5 launches ----
    setup_zero<<<2048, 256>>>();
    setup_weights<<<8192, 256>>>(eWih0, eWhh0, eWih1, eWhh1, dWhh0, dWih1, dWhh1);
    setup_M0<<<dim3(128, 16), 256>>>(dWih0, fcW);
    setup_bias<<<16, 256>>>(ebih0, ebhh0, ebih1, ebhh1, dbih0, dbhh0, dbih1, dbhh1,
                            dWih0, fcb);
    setup_misc<<<4096, 256>>>(fcW, x);

    auto H0 = [](int t) { return (t & 1) ? 1024 : 0; };
    auto H1 = [](int t) { return (t & 1) ? 3072 : 2048; };

    const dim3 gg(32, 4), gb(256);

    // ---- encoder: 82 steps x 2 launches ----
    for (int t = 0; t < TT; t++) {
        gemm_cell<<<gg, gb, SMEM_G>>>(
            Xall + (size_t)t * BB * XALLW, XALLW, Xh + H0(t - 1), XS2, 17,
            We0, KE0, Bias + 0 * GG, C0, lens, t, 1, H0(t), H0(t - 1),
            nullptr, KE0);
        gemm_cell<<<gg, gb, SMEM_G>>>(
            Xh + H0(t), XS2, Xh + H1(t - 1), XS2, 128,
            We1, K2048, Bias + 1 * GG, C1, lens, t, 1, H1(t), H1(t - 1),
            nullptr, K2048);
    }

    // ---- decoder: 100 steps x 2 launches, fc folded / output batched ----
    gemm_cell<<<gg, gb, SMEM_G>>>(
        Xh + H0(-1), XS2, Xh + H0(-1), XS2, 128,
        Wd0, K2048, Bias + 2 * GG, C0, lens, 0, 0, H0(0), H0(-1),
        nullptr, 1024);
    gemm_cell<<<gg, gb, SMEM_G>>>(
        Xh + H0(0), XS2, Xh + H1(-1), XS2, 128,
        Wd1, K2048, Bias + 3 * GG, C1, lens, 0, 0, H1(0), H1(-1),
        H1h + 0, K2048);
    for (int t = 1; t < STEPS; t++) {
        gemm_cell<<<gg, gb, SMEM_G>>>(
            Xh + H0(t - 1), XS2, Xh + H1(t - 1), XS2, 128,
            Wd0, K2048, Bias + 4 * GG, C0, lens, t, 0, H0(t), H0(t - 1),
            nullptr, K2048);
        gemm_cell<<<gg, gb, SMEM_G>>>(
            Xh + H0(t), XS2, Xh + H1(t - 1), XS2, 128,
            Wd1, K2048, Bias + 3 * GG, C1, lens, t, 0, H1(t), H1(t - 1),
            H1h + (size_t)t * BB * HH, K2048);
    }

    // ---- one batched fc for all 100 steps ----
    fc_batch<<<400, gb, SMEM_F>>>(fcb, out);
}

// round 15
// speedup vs baseline: 1.0311x; 1.0311x over previous
#include <cuda_runtime.h>
#include <cuda_fp16.h>
#include <cstdint>

#define BB 512
#define HH 1024
#define GG 4096
#define TT 82
#define DD 129
#define STEPS 100
#define OUTN 128
#define XS2 4096          // Xh row: h0_e(0) h0_o(1024) h1_e(2048) h1_o(3072)
#define XALLW 136
#define KE0 1216
#define K2048 2048

// ===================== device scratch =====================
__device__ __half g_Xh [BB * XS2];      // fp16 state (parity double-buffered)
__device__ float  g_C0 [BB * HH];
__device__ float  g_C1 [BB * HH];
__device__ __half g_Xall[TT * BB * XALLW];   // x permuted+converted, 136-padded
__device__ __half g_H1h [STEPS * BB * HH];   // decoder h1 history for batched fc
__device__ __half g_We0[GG * KE0];      // [Wih0(129)|z(7)|Whh0(1024)|z], gate-interleaved
__device__ __half g_We1[GG * K2048];
__device__ __half g_Wd0[GG * K2048];    // [Whh0 | M0=Wih0@fcW]
__device__ __half g_Wd1[GG * K2048];
__device__ __half g_fcWh[OUTN * HH];
__device__ float  g_bias[5 * GG];       // e0,e1,d0_plain,d1,d0_folded
__device__ int    g_perm[BB];           // sorted pos -> original batch index
__device__ int    g_lenp[BB];           // lengths in sorted order (descending)
__device__ int    g_Mt[TT];             // Mt[t] = #(len > t)

__device__ __forceinline__ uint32_t smem_u32(const void* p) {
    uint32_t a;
    asm("{ .reg .u64 t; cvta.to.shared.u64 t, %1; cvt.u32.u64 %0, t; }" : "=r"(a) : "l"(p));
    return a;
}
__device__ __forceinline__ void cpa16(uint32_t s, const void* g) {
    asm volatile("cp.async.cg.shared.global [%0], [%1], 16;" :: "r"(s), "l"(g));
}
__device__ __forceinline__ void ldsm4(uint32_t (&d)[4], uint32_t addr) {
    asm volatile("ldmatrix.sync.aligned.m8n8.x4.shared.b16 {%0,%1,%2,%3}, [%4];"
                 : "=r"(d[0]), "=r"(d[1]), "=r"(d[2]), "=r"(d[3]) : "r"(addr));
}
__device__ __forceinline__ void mma16816(float (&d)[4], const uint32_t (&a)[4],
                                         uint32_t b0, uint32_t b1) {
    asm volatile("mma.sync.aligned.m16n8k16.row.col.f32.f16.f16.f32 "
                 "{%0,%1,%2,%3},{%4,%5,%6,%7},{%8,%9},{%0,%1,%2,%3};"
                 : "+f"(d[0]), "+f"(d[1]), "+f"(d[2]), "+f"(d[3])
                 : "r"(a[0]), "r"(a[1]), "r"(a[2]), "r"(a[3]), "r"(b0), "r"(b1));
}

// ===================== setup kernels =====================
__global__ void setup_zero() {
    const int n1 = BB * XS2 / 2;   // g_Xh as u32
    const int n2 = BB * HH;
    const int n3 = BB * HH;
    const int total = n1 + n2 + n3;
    for (int i = blockIdx.x * blockDim.x + threadIdx.x; i < total; i += gridDim.x * blockDim.x) {
        if (i < n1) ((uint32_t*)g_Xh)[i] = 0u;
        else if (i < n1 + n2) g_C0[i - n1] = 0.f;
        else g_C1[i - n1 - n2] = 0.f;
    }
}

// deterministic counting sort by length, descending (stable)
__global__ void setup_sort(const int* __restrict__ lengths) {
    __shared__ int hist[TT + 2];
    __shared__ int off[TT + 2];
    const int tid = threadIdx.x;
    if (tid < TT + 2) hist[tid] = 0;
    __syncthreads();
    if (tid == 0) {
        for (int b = 0; b < BB; b++) hist[lengths[b]]++;
        int acc = 0;
        for (int L = TT; L >= 1; L--) { off[L] = acc; acc += hist[L]; }
        for (int b = 0; b < BB; b++) {
            const int L = lengths[b];
            const int pos = off[L]++;
            g_perm[pos] = b;
            g_lenp[pos] = L;
        }
        for (int t = 0; t < TT; t++) {
            int c = 0;
            for (int L = t + 1; L <= TT; L++) c += hist[L];
            g_Mt[t] = c;
        }
    }
}

__global__ void setup_weights(const float* __restrict__ eWih0, const float* __restrict__ eWhh0,
                              const float* __restrict__ eWih1, const float* __restrict__ eWhh1,
                              const float* __restrict__ dWhh0,
                              const float* __restrict__ dWih1, const float* __restrict__ dWhh1) {
    const long S0 = (long)GG * KE0;
    const long S1 = (long)GG * K2048;
    const long S2 = (long)GG * K2048;
    const long S3 = (long)GG * 1024;
    const long total = S0 + S1 + S2 + S3;
    for (long i = blockIdx.x * (long)blockDim.x + threadIdx.x; i < total;
         i += (long)gridDim.x * blockDim.x) {
        if (i < S0) {
            int nd = (int)(i / KE0), k = (int)(i % KE0);
            int n = (nd & 3) * HH + (nd >> 2);
            float v = 0.f;
            if (k < 129) v = eWih0[(size_t)n * 129 + k];
            else if (k >= 136 && k < 1160) v = eWhh0[(size_t)n * 1024 + (k - 136)];
            g_We0[i] = __float2half(v);
        } else if (i < S0 + S1) {
            long j = i - S0;
            int nd = (int)(j / K2048), k = (int)(j % K2048);
            int n = (nd & 3) * HH + (nd >> 2);
            float v = (k < 1024) ? eWih1[(size_t)n * 1024 + k]
                                 : eWhh1[(size_t)n * 1024 + (k - 1024)];
            g_We1[j] = __float2half(v);
        } else if (i < S0 + S1 + S2) {
            long j = i - S0 - S1;
            int nd = (int)(j / K2048), k = (int)(j % K2048);
            int n = (nd & 3) * HH + (nd >> 2);
            float v = (k < 1024) ? dWih1[(size_t)n * 1024 + k]
                                 : dWhh1[(size_t)n * 1024 + (k - 1024)];
            g_Wd1[j] = __float2half(v);
        } else {
            long j = i - S0 - S1 - S2;
            int nd = (int)(j / 1024), k = (int)(j % 1024);
            int n = (nd & 3) * HH + (nd >> 2);
            g_Wd0[(size_t)nd * K2048 + k] = __float2half(dWhh0[(size_t)n * 1024 + k]);
        }
    }
}

// Wd0[:, 1024:2048] = M0 = Wih0 @ fcW
__global__ void setup_M0(const float* __restrict__ dWih0, const float* __restrict__ fcW) {
    __shared__ float sW[32][128];
    __shared__ float sF[128][64];
    const int nd0 = blockIdx.x * 32;
    const int k0  = blockIdx.y * 64;
    const int tid = threadIdx.x;
    for (int i = tid; i < 32 * 128; i += 256) {
        int r = i >> 7, o = i & 127;
        int nd = nd0 + r, n = (nd & 3) * HH + (nd >> 2);
        sW[r][o] = dWih0[(size_t)n * 128 + o];
    }
    for (int i = tid; i < 128 * 64; i += 256) {
        int o = i >> 6, kk = i & 63;
        sF[o][kk] = fcW[(size_t)o * HH + k0 + kk];
    }
    __syncthreads();
    for (int i = tid; i < 32 * 64; i += 256) {
        int r = i >> 6, kk = i & 63;
        float acc = 0.f;
#pragma unroll 16
        for (int o = 0; o < 128; o++) acc += sW[r][o] * sF[o][kk];
        g_Wd0[(size_t)(nd0 + r) * K2048 + 1024 + k0 + kk] = __float2half(acc);
    }
}

__global__ void setup_bias(const float* eb0a, const float* eb0b,
                           const float* eb1a, const float* eb1b,
                           const float* db0a, const float* db0b,
                           const float* db1a, const float* db1b,
                           const float* __restrict__ dWih0, const float* __restrict__ fcb) {
    int nd = blockIdx.x * blockDim.x + threadIdx.x;
    if (nd >= GG) return;
    int n = (nd & 3) * HH + (nd >> 2);
    g_bias[0 * GG + nd] = eb0a[n] + eb0b[n];
    g_bias[1 * GG + nd] = eb1a[n] + eb1b[n];
    float d0 = db0a[n] + db0b[n];
    g_bias[2 * GG + nd] = d0;
    g_bias[3 * GG + nd] = db1a[n] + db1b[n];
    float acc = 0.f;
#pragma unroll 16
    for (int o = 0; o < 128; o++) acc += dWih0[(size_t)n * 128 + o] * fcb[o];
    g_bias[4 * GG + nd] = d0 + acc;
}

// fcW -> fp16 + x -> g_Xall PERMUTED (must run after setup_sort)
__global__ void setup_misc(const float* __restrict__ fcW, const float* __restrict__ x) {
    const int t1 = OUTN * HH;
    const int t2 = TT * BB * XALLW;
    for (int i = blockIdx.x * blockDim.x + threadIdx.x; i < t1 + t2;
         i += gridDim.x * blockDim.x) {
        if (i < t1) {
            g_fcWh[i] = __float2half(fcW[i]);
        } else {
            int j = i - t1;
            int tt = j / (BB * XALLW);
            int r = j % (BB * XALLW);
            int bs = r / XALLW, k = r % XALLW;
            const int b = g_perm[bs];
            float v = (k < DD) ? x[(size_t)b * (TT * DD) + tt * DD + k] : 0.f;
            g_Xall[j] = __float2half(v);
        }
    }
}

// after encoder: copy each row's FINAL h0/h1 (parity (len-1)&1) into odd slots
__global__ void fixup_h() {
    const int idx = blockIdx.x * blockDim.x + threadIdx.x;
    if (idx >= BB * HH) return;
    const int b = idx >> 10, j = idx & 1023;
    const int p = (g_lenp[b] - 1) & 1;
    const size_t row = (size_t)b * XS2;
    const __half h0f = g_Xh[row + p * 1024 + j];
    const __half h1f = g_Xh[row + 2048 + p * 1024 + j];
    g_Xh[row + 1024 + j] = h0f;
    g_Xh[row + 3072 + j] = h1f;
}

// ===================== fused GEMM + LSTM cell =====================
#define TBYTES 16384
#define STAGE_B (2 * TBYTES)      // 32 KB
#define SMEM_G  (4 * STAGE_B)     // 128 KB: 4-stage, single sync per chunk
#define SMEM_F  (3 * STAGE_B)     // 96 KB: fc_batch 3-stage

#define GEMM_PROLOGUE()                                                            \
    const uint32_t sb = smem_u32(smem);                                            \
    const int tid = threadIdx.x;                                                   \
    const int l = tid & 31;                                                        \
    const int wid = tid >> 5;                                                      \
    const int warp_m = wid >> 2;                                                   \
    const int warp_n = wid & 3;                                                    \
    const int rowL = tid >> 3;                                                     \
    const int colL = tid & 7;                                                      \
    const uint32_t swL = (uint32_t)(colL ^ (rowL & 7)) * 16;                       \
    uint32_t arow[4], ar7[4];                                                      \
    _Pragma("unroll")                                                              \
    for (int wm = 0; wm < 4; wm++) {                                               \
        const uint32_t r = warp_m * 64 + wm * 16 + (l & 15);                       \
        arow[wm] = r * 128; ar7[wm] = r & 7;                                       \
    }                                                                              \
    uint32_t brow[2], br7[2];                                                      \
    _Pragma("unroll")                                                              \
    for (int p = 0; p < 2; p++) {                                                  \
        const uint32_t r = warp_n * 32 + p * 16 + ((l >> 4) << 3) + (l & 7);       \
        brow[p] = r * 128; br7[p] = r & 7;                                         \
    }                                                                              \
    const uint32_t acsel = (uint32_t)(l >> 4);                                     \
    const uint32_t bcsel = (uint32_t)((l >> 3) & 1);                               \
    float acc[4][4][4];                                                            \
    _Pragma("unroll")                                                              \
    for (int i = 0; i < 4; i++)                                                    \
        _Pragma("unroll")                                                          \
        for (int j = 0; j < 4; j++)                                                \
            _Pragma("unroll")                                                      \
            for (int q = 0; q < 4; q++) acc[i][j][q] = 0.f;

#define GEMM_COMPUTE_CHUNK(st)                                                     \
    _Pragma("unroll")                                                              \
    for (int ks = 0; ks < 4; ks++) {                                               \
        uint32_t AH[4][4], BH[2][4];                                               \
        _Pragma("unroll")                                                          \
        for (int wm = 0; wm < 4; wm++) {                                           \
            const uint32_t c = (uint32_t)(2 * ks) + acsel;                         \
            ldsm4(AH[wm], (st) + arow[wm] + ((c ^ ar7[wm]) << 4));                 \
        }                                                                          \
        _Pragma("unroll")                                                          \
        for (int p = 0; p < 2; p++) {                                              \
            const uint32_t c = (uint32_t)(2 * ks) + bcsel;                         \
            ldsm4(BH[p], (st) + TBYTES + brow[p] + ((c ^ br7[p]) << 4));           \
        }                                                                          \
        _Pragma("unroll")                                                          \
        for (int wm = 0; wm < 4; wm++) {                                           \
            _Pragma("unroll")                                                      \
            for (int wn = 0; wn < 4; wn++) {                                       \
                const int p = wn >> 1, h = (wn & 1) << 1;                          \
                mma16816(acc[wm][wn], AH[wm], BH[p][h], BH[p][h + 1]);             \
            }                                                                      \
        }                                                                          \
    }

#define GEMM_MAINLOOP4(LOADCHUNK)                                                  \
    LOADCHUNK(0, 0);                                                               \
    LOADCHUNK(1, 1);                                                               \
    LOADCHUNK(2, 2);                                                               \
    for (int kc = 0; kc < nch; kc++) {                                             \
        if (kc + 2 < nch) { asm volatile("cp.async.wait_group 2;"); }              \
        else if (kc + 1 < nch) { asm volatile("cp.async.wait_group 1;"); }         \
        else { asm volatile("cp.async.wait_group 0;"); }                           \
        __syncthreads();                                                           \
        if (kc + 3 < nch) LOADCHUNK((kc + 3) & 3, kc + 3);                         \
        const uint32_t st = sb + (uint32_t)(kc & 3) * STAGE_B;                     \
        GEMM_COMPUTE_CHUNK(st);                                                    \
    }                                                                              \
    __syncthreads();

#define GEMM_ACC_TO_SMEM(biasptr)                                                  \
    float* cs = (float*)smem;                                                      \
    _Pragma("unroll")                                                              \
    for (int wn = 0; wn < 4; wn++) {                                               \
        const int cl = warp_n * 32 + wn * 8 + (l & 3) * 2;                         \
        const float2 bv = *(const float2*)((biasptr) + cl);                        \
        _Pragma("unroll")                                                          \
        for (int wm = 0; wm < 4; wm++) {                                           \
            const int rl = warp_m * 64 + wm * 16 + (l >> 2);                       \
            cs[rl * 132 + cl]           = acc[wm][wn][0] + bv.x;                   \
            cs[rl * 132 + cl + 1]       = acc[wm][wn][1] + bv.y;                   \
            cs[(rl + 8) * 132 + cl]     = acc[wm][wn][2] + bv.x;                   \
            cs[(rl + 8) * 132 + cl + 1] = acc[wm][wn][3] + bv.y;                   \
        }                                                                          \
    }                                                                              \
    __syncthreads();

__global__ __launch_bounds__(256, 1)
void gemm_cell(const __half* __restrict__ A1, int ld1,
               const __half* __restrict__ A2, int ld2, int bnd,
               const __half* __restrict__ W, int ldw,
               const float* __restrict__ bias,
               float* __restrict__ Cc,
               int enc_t,                       // >=0: encoder step (Mt active rows); -1: decoder
               int hW,
               __half* __restrict__ hist,       // decL1: h1 history slice, else null
               int K) {
    extern __shared__ char smem[];
    const int m0 = (int)blockIdx.y * 128;
    const int n0 = (int)blockIdx.x * 128;

    const int Mt = (enc_t >= 0) ? g_Mt[enc_t] : BB;
    if (m0 >= Mt) return;                       // whole M-tile frozen: skip

    GEMM_PROLOGUE();

    const size_t ld1B = (size_t)ld1 * 2, ld2B = (size_t)ld2 * 2;
    const size_t ldwB = (size_t)ldw * 2;
    const char* pA1 = (const char*)A1 + (size_t)(m0 + rowL) * ld1B;
    const char* pA2 = (const char*)A2 + (size_t)(m0 + rowL) * ld2B;
    const char* pW  = (const char*)W  + (size_t)(n0 + rowL) * ldwB;
    const int nch = K >> 6;

#define LOADCHUNK_C(s, kc) do {                                                    \
    const uint32_t st_ = sb + (uint32_t)(s) * STAGE_B;                             \
    const int gcol_ = (kc) * 8 + colL;                                             \
    const char* ap_; size_t astep_;                                                \
    if (gcol_ < bnd) { ap_ = pA1 + (size_t)gcol_ * 16; astep_ = ld1B * 32; }       \
    else { ap_ = pA2 + (size_t)(gcol_ - bnd) * 16; astep_ = ld2B * 32; }           \
    const char* wp_ = pW + (size_t)gcol_ * 16;                                     \
    _Pragma("unroll")                                                              \
    for (int it = 0; it < 4; it++) {                                               \
        const uint32_t so_ = (uint32_t)(rowL + 32 * it) * 128 + swL;               \
        cpa16(st_ + so_, ap_ + (size_t)it * astep_);                               \
        cpa16(st_ + TBYTES + so_, wp_ + (size_t)(32 * it) * ldwB);                 \
    }                                                                              \
    asm volatile("cp.async.commit_group;");                                        \
} while (0)

    GEMM_MAINLOOP4(LOADCHUNK_C);
    GEMM_ACC_TO_SMEM(bias + n0);

    // ---- LSTM cell: write only active rows (m < Mt) ----
    const int ch0 = n0 >> 2;
#pragma unroll
    for (int it = 0; it < 16; it++) {
        const int idx = it * 256 + tid;
        const int bl = idx >> 5;
        const int jl = idx & 31;
        const int b = m0 + bl;
        if (b >= Mt) continue;
        const float4 v = *(const float4*)&cs[bl * 132 + 4 * jl];
        const int j = ch0 + jl;
        const float ig = 1.f / (1.f + __expf(-v.x));
        const float fg = 1.f / (1.f + __expf(-v.y));
        const float gg = tanhf(v.z);
        const float og = 1.f / (1.f + __expf(-v.w));
        const size_t cidx = (size_t)b * HH + j;
        const float cn = fg * Cc[cidx] + ig * gg;
        const float hn = og * tanhf(cn);
        Cc[cidx] = cn;
        const __half hh = __float2half(hn);
        g_Xh[(size_t)b * XS2 + hW + j] = hh;
        if (hist) hist[(size_t)b * HH + j] = hh;
    }
}

// ===================== batched fc: out = H1hist @ fcW^T + fcb (one launch) =====================
__global__ __launch_bounds__(256, 1)
void fc_batch(const float* __restrict__ fcb, float* __restrict__ out) {
    extern __shared__ char smem[];
    const int m0 = (int)blockIdx.x * 128;     // m = t*BB + b_sorted

    GEMM_PROLOGUE();

    const size_t ldaB = (size_t)HH * 2;
    const char* pA = (const char*)g_H1h + (size_t)(m0 + rowL) * ldaB + colL * 16;
    const char* pW = (const char*)g_fcWh + (size_t)rowL * ldaB + colL * 16;
    const int nch = HH >> 6;

#define LOADCHUNK_F(s, kc) do {                                                    \
    const uint32_t st_ = sb + (uint32_t)(s) * STAGE_B;                             \
    const size_t ko_ = (size_t)(kc) * 128;                                         \
    _Pragma("unroll")                                                              \
    for (int it = 0; it < 4; it++) {                                               \
        const uint32_t so_ = (uint32_t)(rowL + 32 * it) * 128 + swL;               \
        cpa16(st_ + so_, pA + ko_ + (size_t)(32 * it) * ldaB);                     \
        cpa16(st_ + TBYTES + so_, pW + ko_ + (size_t)(32 * it) * ldaB);            \
    }                                                                              \
    asm volatile("cp.async.commit_group;");                                        \
} while (0)

    LOADCHUNK_F(0, 0);
    LOADCHUNK_F(1, 1);
    for (int kc = 0; kc < nch; kc++) {
        if (kc + 1 < nch) { asm volatile("cp.async.wait_group 1;"); }
        else { asm volatile("cp.async.wait_group 0;"); }
        __syncthreads();
        if (kc + 2 < nch) { const int s_ = (kc + 2) % 3; LOADCHUNK_F(s_, kc + 2); }
        const uint32_t st = sb + (uint32_t)(kc % 3) * STAGE_B;
        GEMM_COMPUTE_CHUNK(st);
        __syncthreads();
    }

    GEMM_ACC_TO_SMEM(fcb);

    // store: m = t*BB + b_sorted -> out[(perm[b_sorted]*STEPS + t)*OUTN + n]
#pragma unroll
    for (int it = 0; it < 16; it++) {
        const int idx = it * 256 + tid;
        const int bl = idx >> 5;
        const int jl = idx & 31;
        const int m = m0 + bl;
        const int bs = m & (BB - 1);
        const int tt = m >> 9;
        const int b = g_perm[bs];
        const float4 v = *(const float4*)&cs[bl * 132 + 4 * jl];
        *(float4*)&out[((size_t)b * STEPS + tt) * OUTN + 4 * jl] = v;
    }
}

// ===================== host =====================
extern "C" void kernel_launch(void* const* d_in, const int* in_sizes, int n_in,
                              void* d_out, int out_size) {
    const float* x     = (const float*)d_in[0];
    const int*   lens  = (const int*)  d_in[1];
    const float* eWih0 = (const float*)d_in[2];
    const float* eWhh0 = (const float*)d_in[3];
    const float* ebih0 = (const float*)d_in[4];
    const float* ebhh0 = (const float*)d_in[5];
    const float* eWih1 = (const float*)d_in[6];
    const float* eWhh1 = (const float*)d_in[7];
    const float* ebih1 = (const float*)d_in[8];
    const float* ebhh1 = (const float*)d_in[9];
    const float* dWih0 = (const float*)d_in[10];
    const float* dWhh0 = (const float*)d_in[11];
    const float* dbih0 = (const float*)d_in[12];
    const float* dbhh0 = (const float*)d_in[13];
    const float* dWih1 = (const float*)d_in[14];
    const float* dWhh1 = (const float*)d_in[15];
    const float* dbih1 = (const float*)d_in[16];
    const float* dbhh1 = (const float*)d_in[17];
    const float* fcW   = (const float*)d_in[18];
    const float* fcb   = (const float*)d_in[19];
    float* out = (float*)d_out;

    float *Bias, *C0, *C1;
    __half *Xh, *Xall, *We0, *We1, *Wd0, *Wd1, *H1h;
    cudaGetSymbolAddress((void**)&C0,   g_C0);
    cudaGetSymbolAddress((void**)&C1,   g_C1);
    cudaGetSymbolAddress((void**)&Bias, g_bias);
    cudaGetSymbolAddress((void**)&Xh,   g_Xh);
    cudaGetSymbolAddress((void**)&Xall, g_Xall);
    cudaGetSymbolAddress((void**)&We0,  g_We0);
    cudaGetSymbolAddress((void**)&We1,  g_We1);
    cudaGetSymbolAddress((void**)&Wd0,  g_Wd0);
    cudaGetSymbolAddress((void**)&Wd1,  g_Wd1);
    cudaGetSymbolAddress((void**)&H1h,  g_H1h);

    cudaFuncSetAttribute(gemm_cell, cudaFuncAttributeMaxDynamicSharedMemorySize, SMEM_G);
    cudaFuncSetAttribute(fc_batch,  cudaFuncAttributeMaxDynamicSharedMemorySize, SMEM_F);

    // ---- setup ----
    setup_zero<<<2048, 256>>>();
    setup_sort<<<1, 128>>>(lens);
    setup_weights<<<8192, 256>>>(eWih0, eWhh0, eWih1, eWhh1, dWhh0, dWih1, dWhh1);
    setup_M0<<<dim3(128, 16), 256>>>(dWih0, fcW);
    setup_bias<<<16, 256>>>(ebih0, ebhh0, ebih1, ebhh1, dbih0, dbhh0, dbih1, dbhh1,
                            dWih0, fcb);
    setup_misc<<<4096, 256>>>(fcW, x);   // uses g_perm (after setup_sort)

    auto H0 = [](int t) { return (t & 1) ? 1024 : 0; };
    auto H1 = [](int t) { return (t & 1) ? 3072 : 2048; };

    const dim3 gg(32, 4), gb(256);

    // ---- encoder: 82 steps x 2 launches (tiles beyond Mt early-exit) ----
    for (int t = 0; t < TT; t++) {
        gemm_cell<<<gg, gb, SMEM_G>>>(
            Xall + (size_t)t * BB * XALLW, XALLW, Xh + H0(t - 1), XS2, 17,
            We0, KE0, Bias + 0 * GG, C0, t, H0(t), nullptr, KE0);
        gemm_cell<<<gg, gb, SMEM_G>>>(
            Xh + H0(t), XS2, Xh + H1(t - 1), XS2, 128,
            We1, K2048, Bias + 1 * GG, C1, t, H1(t), nullptr, K2048);
    }

    // ---- fix-up: final h0/h1 (parity (len-1)&1) -> odd slots for decoder t=0 ----
    fixup_h<<<(BB * HH + 255) / 256, 256>>>();

    // ---- decoder: 100 steps x 2 launches, fc folded / output batched ----
    gemm_cell<<<gg, gb, SMEM_G>>>(
        Xh + H0(-1), XS2, Xh + H0(-1), XS2, 128,
        Wd0, K2048, Bias + 2 * GG, C0, -1, H0(0), nullptr, 1024);
    gemm_cell<<<gg, gb, SMEM_G>>>(
        Xh + H0(0), XS2, Xh + H1(-1), XS2, 128,
        Wd1, K2048, Bias + 3 * GG, C1, -1, H1(0), H1h + 0, K2048);
    for (int t = 1; t < STEPS; t++) {
        gemm_cell<<<gg, gb, SMEM_G>>>(
            Xh + H0(t - 1), XS2, Xh + H1(t - 1), XS2, 128,
            Wd0, K2048, Bias + 4 * GG, C0, -1, H0(t), nullptr, K2048);
        gemm_cell<<<gg, gb, SMEM_G>>>(
            Xh + H0(t), XS2, Xh + H1(t - 1), XS2, 128,
            Wd1, K2048, Bias + 3 * GG, C1, -1, H1(t), H1h + (size_t)t * BB * HH, K2048);
    }

    // ---- one batched fc for all 100 steps (un-permutes on store) ----
    fc_batch<<<400, gb, SMEM_F>>>(fcb, out);
}

// round 16
// speedup vs baseline: 1.1218x; 1.0880x over previous
#include <cuda_runtime.h>
#include <cuda_fp16.h>
#include <cstdint>

#define BB 512
#define HH 1024
#define GG 4096
#define TT 82
#define DD 129
#define STEPS 100
#define OUTN 128
#define XS2 4096          // Xh row: h0_e(0) h0_o(1024) h1_e(2048) h1_o(3072)
#define XALLW 136
#define KE0 1216
#define K2048 2048
#define FUSE_T 42         // fuse encL1(t)+encL0(t+1) for t >= FUSE_T (perf-only threshold)

// ===================== device scratch =====================
__device__ __half g_Xh [BB * XS2];      // fp16 state (parity double-buffered)
__device__ float  g_C0 [BB * HH];
__device__ float  g_C1 [BB * HH];
__device__ __half g_Xall[TT * BB * XALLW];   // x permuted+converted, 136-padded
__device__ __half g_H1h [STEPS * BB * HH];   // decoder h1 history for batched fc
__device__ __half g_We0[GG * KE0];      // [Wih0(129)|z(7)|Whh0(1024)|z], gate-interleaved
__device__ __half g_We1[GG * K2048];
__device__ __half g_Wd0[GG * K2048];    // [Whh0 | M0=Wih0@fcW]
__device__ __half g_Wd1[GG * K2048];
__device__ __half g_fcWh[OUTN * HH];
__device__ float  g_bias[5 * GG];       // e0,e1,d0_plain,d1,d0_folded
__device__ int    g_perm[BB];           // sorted pos -> original batch index
__device__ int    g_lenp[BB];           // lengths in sorted order (descending)
__device__ int    g_Mt[TT + 1];         // Mt[t] = #(len > t); Mt[TT] = 0

__device__ __forceinline__ uint32_t smem_u32(const void* p) {
    uint32_t a;
    asm("{ .reg .u64 t; cvta.to.shared.u64 t, %1; cvt.u32.u64 %0, t; }" : "=r"(a) : "l"(p));
    return a;
}
__device__ __forceinline__ void cpa16(uint32_t s, const void* g) {
    asm volatile("cp.async.cg.shared.global [%0], [%1], 16;" :: "r"(s), "l"(g));
}
__device__ __forceinline__ void ldsm4(uint32_t (&d)[4], uint32_t addr) {
    asm volatile("ldmatrix.sync.aligned.m8n8.x4.shared.b16 {%0,%1,%2,%3}, [%4];"
                 : "=r"(d[0]), "=r"(d[1]), "=r"(d[2]), "=r"(d[3]) : "r"(addr));
}
__device__ __forceinline__ void mma16816(float (&d)[4], const uint32_t (&a)[4],
                                         uint32_t b0, uint32_t b1) {
    asm volatile("mma.sync.aligned.m16n8k16.row.col.f32.f16.f16.f32 "
                 "{%0,%1,%2,%3},{%4,%5,%6,%7},{%8,%9},{%0,%1,%2,%3};"
                 : "+f"(d[0]), "+f"(d[1]), "+f"(d[2]), "+f"(d[3])
                 : "r"(a[0]), "r"(a[1]), "r"(a[2]), "r"(a[3]), "r"(b0), "r"(b1));
}

// ===================== setup kernels =====================
__global__ void setup_zero() {
    const int n1 = BB * XS2 / 2;   // g_Xh as u32
    const int n2 = BB * HH;
    const int n3 = BB * HH;
    const int total = n1 + n2 + n3;
    for (int i = blockIdx.x * blockDim.x + threadIdx.x; i < total; i += gridDim.x * blockDim.x) {
        if (i < n1) ((uint32_t*)g_Xh)[i] = 0u;
        else if (i < n1 + n2) g_C0[i - n1] = 0.f;
        else g_C1[i - n1 - n2] = 0.f;
    }
}

// deterministic counting sort by length, descending (stable)
__global__ void setup_sort(const int* __restrict__ lengths) {
    __shared__ int hist[TT + 2];
    __shared__ int off[TT + 2];
    const int tid = threadIdx.x;
    if (tid < TT + 2) hist[tid] = 0;
    __syncthreads();
    if (tid == 0) {
        for (int b = 0; b < BB; b++) hist[lengths[b]]++;
        int acc = 0;
        for (int L = TT; L >= 1; L--) { off[L] = acc; acc += hist[L]; }
        for (int b = 0; b < BB; b++) {
            const int L = lengths[b];
            const int pos = off[L]++;
            g_perm[pos] = b;
            g_lenp[pos] = L;
        }
        for (int t = 0; t < TT; t++) {
            int c = 0;
            for (int L = t + 1; L <= TT; L++) c += hist[L];
            g_Mt[t] = c;
        }
        g_Mt[TT] = 0;
    }
}

__global__ void setup_weights(const float* __restrict__ eWih0, const float* __restrict__ eWhh0,
                              const float* __restrict__ eWih1, const float* __restrict__ eWhh1,
                              const float* __restrict__ dWhh0,
                              const float* __restrict__ dWih1, const float* __restrict__ dWhh1) {
    const long S0 = (long)GG * KE0;
    const long S1 = (long)GG * K2048;
    const long S2 = (long)GG * K2048;
    const long S3 = (long)GG * 1024;
    const long total = S0 + S1 + S2 + S3;
    for (long i = blockIdx.x * (long)blockDim.x + threadIdx.x; i < total;
         i += (long)gridDim.x * blockDim.x) {
        if (i < S0) {
            int nd = (int)(i / KE0), k = (int)(i % KE0);
            int n = (nd & 3) * HH + (nd >> 2);
            float v = 0.f;
            if (k < 129) v = eWih0[(size_t)n * 129 + k];
            else if (k >= 136 && k < 1160) v = eWhh0[(size_t)n * 1024 + (k - 136)];
            g_We0[i] = __float2half(v);
        } else if (i < S0 + S1) {
            long j = i - S0;
            int nd = (int)(j / K2048), k = (int)(j % K2048);
            int n = (nd & 3) * HH + (nd >> 2);
            float v = (k < 1024) ? eWih1[(size_t)n * 1024 + k]
                                 : eWhh1[(size_t)n * 1024 + (k - 1024)];
            g_We1[j] = __float2half(v);
        } else if (i < S0 + S1 + S2) {
            long j = i - S0 - S1;
            int nd = (int)(j / K2048), k = (int)(j % K2048);
            int n = (nd & 3) * HH + (nd >> 2);
            float v = (k < 1024) ? dWih1[(size_t)n * 1024 + k]
                                 : dWhh1[(size_t)n * 1024 + (k - 1024)];
            g_Wd1[j] = __float2half(v);
        } else {
            long j = i - S0 - S1 - S2;
            int nd = (int)(j / 1024), k = (int)(j % 1024);
            int n = (nd & 3) * HH + (nd >> 2);
            g_Wd0[(size_t)nd * K2048 + k] = __float2half(dWhh0[(size_t)n * 1024 + k]);
        }
    }
}

// Wd0[:, 1024:2048] = M0 = Wih0 @ fcW
__global__ void setup_M0(const float* __restrict__ dWih0, const float* __restrict__ fcW) {
    __shared__ float sW[32][128];
    __shared__ float sF[128][64];
    const int nd0 = blockIdx.x * 32;
    const int k0  = blockIdx.y * 64;
    const int tid = threadIdx.x;
    for (int i = tid; i < 32 * 128; i += 256) {
        int r = i >> 7, o = i & 127;
        int nd = nd0 + r, n = (nd & 3) * HH + (nd >> 2);
        sW[r][o] = dWih0[(size_t)n * 128 + o];
    }
    for (int i = tid; i < 128 * 64; i += 256) {
        int o = i >> 6, kk = i & 63;
        sF[o][kk] = fcW[(size_t)o * HH + k0 + kk];
    }
    __syncthreads();
    for (int i = tid; i < 32 * 64; i += 256) {
        int r = i >> 6, kk = i & 63;
        float acc = 0.f;
#pragma unroll 16
        for (int o = 0; o < 128; o++) acc += sW[r][o] * sF[o][kk];
        g_Wd0[(size_t)(nd0 + r) * K2048 + 1024 + k0 + kk] = __float2half(acc);
    }
}

__global__ void setup_bias(const float* eb0a, const float* eb0b,
                           const float* eb1a, const float* eb1b,
                           const float* db0a, const float* db0b,
                           const float* db1a, const float* db1b,
                           const float* __restrict__ dWih0, const float* __restrict__ fcb) {
    int nd = blockIdx.x * blockDim.x + threadIdx.x;
    if (nd >= GG) return;
    int n = (nd & 3) * HH + (nd >> 2);
    g_bias[0 * GG + nd] = eb0a[n] + eb0b[n];
    g_bias[1 * GG + nd] = eb1a[n] + eb1b[n];
    float d0 = db0a[n] + db0b[n];
    g_bias[2 * GG + nd] = d0;
    g_bias[3 * GG + nd] = db1a[n] + db1b[n];
    float acc = 0.f;
#pragma unroll 16
    for (int o = 0; o < 128; o++) acc += dWih0[(size_t)n * 128 + o] * fcb[o];
    g_bias[4 * GG + nd] = d0 + acc;
}

// fcW -> fp16 + x -> g_Xall PERMUTED (after setup_sort)
__global__ void setup_misc(const float* __restrict__ fcW, const float* __restrict__ x) {
    const int t1 = OUTN * HH;
    const int t2 = TT * BB * XALLW;
    for (int i = blockIdx.x * blockDim.x + threadIdx.x; i < t1 + t2;
         i += gridDim.x * blockDim.x) {
        if (i < t1) {
            g_fcWh[i] = __float2half(fcW[i]);
        } else {
            int j = i - t1;
            int tt = j / (BB * XALLW);
            int r = j % (BB * XALLW);
            int bs = r / XALLW, k = r % XALLW;
            const int b = g_perm[bs];
            float v = (k < DD) ? x[(size_t)b * (TT * DD) + tt * DD + k] : 0.f;
            g_Xall[j] = __float2half(v);
        }
    }
}

// after encoder: copy final h0/h1 (parity (len-1)&1) into odd slots for dec t=0
__global__ void fixup_h() {
    const int idx = blockIdx.x * blockDim.x + threadIdx.x;
    if (idx >= BB * HH) return;
    const int b = idx >> 10, j = idx & 1023;
    const int p = (g_lenp[b] - 1) & 1;
    const size_t row = (size_t)b * XS2;
    const __half h0f = g_Xh[row + p * 1024 + j];
    const __half h1f = g_Xh[row + 2048 + p * 1024 + j];
    g_Xh[row + 1024 + j] = h0f;
    g_Xh[row + 3072 + j] = h1f;
}

// ===================== fused GEMM + LSTM cell =====================
#define TBYTES 16384
#define STAGE_B (2 * TBYTES)      // 32 KB
#define SMEM_G  (4 * STAGE_B)     // 128 KB: 4-stage, single sync per chunk
#define SMEM_F  (3 * STAGE_B)     // 96 KB: fc_batch 3-stage

#define GEMM_PROLOGUE()                                                            \
    const uint32_t sb = smem_u32(smem);                                            \
    const int tid = threadIdx.x;                                                   \
    const int l = tid & 31;                                                        \
    const int wid = tid >> 5;                                                      \
    const int warp_m = wid >> 2;                                                   \
    const int warp_n = wid & 3;                                                    \
    const int rowL = tid >> 3;                                                     \
    const int colL = tid & 7;                                                      \
    const uint32_t swL = (uint32_t)(colL ^ (rowL & 7)) * 16;                       \
    uint32_t arow[4], ar7[4];                                                      \
    _Pragma("unroll")                                                              \
    for (int wm = 0; wm < 4; wm++) {                                               \
        const uint32_t r = warp_m * 64 + wm * 16 + (l & 15);                       \
        arow[wm] = r * 128; ar7[wm] = r & 7;                                       \
    }                                                                              \
    uint32_t brow[2], br7[2];                                                      \
    _Pragma("unroll")                                                              \
    for (int p = 0; p < 2; p++) {                                                  \
        const uint32_t r = warp_n * 32 + p * 16 + ((l >> 4) << 3) + (l & 7);       \
        brow[p] = r * 128; br7[p] = r & 7;                                         \
    }                                                                              \
    const uint32_t acsel = (uint32_t)(l >> 4);                                     \
    const uint32_t bcsel = (uint32_t)((l >> 3) & 1);                               \
    float acc[4][4][4];                                                            \
    _Pragma("unroll")                                                              \
    for (int i = 0; i < 4; i++)                                                    \
        _Pragma("unroll")                                                          \
        for (int j = 0; j < 4; j++)                                                \
            _Pragma("unroll")                                                      \
            for (int q = 0; q < 4; q++) acc[i][j][q] = 0.f;

#define GEMM_COMPUTE_CHUNK(st)                                                     \
    _Pragma("unroll")                                                              \
    for (int ks = 0; ks < 4; ks++) {                                               \
        uint32_t AH[4][4], BH[2][4];                                               \
        _Pragma("unroll")                                                          \
        for (int wm = 0; wm < 4; wm++) {                                           \
            const uint32_t c = (uint32_t)(2 * ks) + acsel;                         \
            ldsm4(AH[wm], (st) + arow[wm] + ((c ^ ar7[wm]) << 4));                 \
        }                                                                          \
        _Pragma("unroll")                                                          \
        for (int p = 0; p < 2; p++) {                                              \
            const uint32_t c = (uint32_t)(2 * ks) + bcsel;                         \
            ldsm4(BH[p], (st) + TBYTES + brow[p] + ((c ^ br7[p]) << 4));           \
        }                                                                          \
        _Pragma("unroll")                                                          \
        for (int wm = 0; wm < 4; wm++) {                                           \
            _Pragma("unroll")                                                      \
            for (int wn = 0; wn < 4; wn++) {                                       \
                const int p = wn >> 1, h = (wn & 1) << 1;                          \
                mma16816(acc[wm][wn], AH[wm], BH[p][h], BH[p][h + 1]);             \
            }                                                                      \
        }                                                                          \
    }

#define GEMM_MAINLOOP4(LOADCHUNK)                                                  \
    LOADCHUNK(0, 0);                                                               \
    LOADCHUNK(1, 1);                                                               \
    LOADCHUNK(2, 2);                                                               \
    for (int kc = 0; kc < nch; kc++) {                                             \
        if (kc + 2 < nch) { asm volatile("cp.async.wait_group 2;"); }              \
        else if (kc + 1 < nch) { asm volatile("cp.async.wait_group 1;"); }         \
        else { asm volatile("cp.async.wait_group 0;"); }                           \
        __syncthreads();                                                           \
        if (kc + 3 < nch) LOADCHUNK((kc + 3) & 3, kc + 3);                         \
        const uint32_t st = sb + (uint32_t)(kc & 3) * STAGE_B;                     \
        GEMM_COMPUTE_CHUNK(st);                                                    \
    }                                                                              \
    __syncthreads();

#define GEMM_ACC_TO_SMEM(biasptr)                                                  \
    float* cs = (float*)smem;                                                      \
    _Pragma("unroll")                                                              \
    for (int wn = 0; wn < 4; wn++) {                                               \
        const int cl = warp_n * 32 + wn * 8 + (l & 3) * 2;                         \
        const float2 bv = *(const float2*)((biasptr) + cl);                        \
        _Pragma("unroll")                                                          \
        for (int wm = 0; wm < 4; wm++) {                                           \
            const int rl = warp_m * 64 + wm * 16 + (l >> 2);                       \
            cs[rl * 132 + cl]           = acc[wm][wn][0] + bv.x;                   \
            cs[rl * 132 + cl + 1]       = acc[wm][wn][1] + bv.y;                   \
            cs[(rl + 8) * 132 + cl]     = acc[wm][wn][2] + bv.x;                   \
            cs[(rl + 8) * 132 + cl + 1] = acc[wm][wn][3] + bv.y;                   \
        }                                                                          \
    }                                                                              \
    __syncthreads();

// common loader (two-source A + W), used by gemm_cell and enc_pair
#define LOADCHUNK_C(s, kc) do {                                                    \
    const uint32_t st_ = sb + (uint32_t)(s) * STAGE_B;                             \
    const int gcol_ = (kc) * 8 + colL;                                             \
    const char* ap_; size_t astep_;                                                \
    if (gcol_ < bnd) { ap_ = pA1 + (size_t)gcol_ * 16; astep_ = ld1B * 32; }       \
    else { ap_ = pA2 + (size_t)(gcol_ - bnd) * 16; astep_ = ld2B * 32; }           \
    const char* wp_ = pW + (size_t)gcol_ * 16;                                     \
    _Pragma("unroll")                                                              \
    for (int it = 0; it < 4; it++) {                                               \
        const uint32_t so_ = (uint32_t)(rowL + 32 * it) * 128 + swL;               \
        cpa16(st_ + so_, ap_ + (size_t)it * astep_);                               \
        cpa16(st_ + TBYTES + so_, wp_ + (size_t)(32 * it) * ldwB);                 \
    }                                                                              \
    asm volatile("cp.async.commit_group;");                                        \
} while (0)

// LSTM cell epilogue on rows [m0, min(m0+128, Mt))
#define CELL_EPILOGUE(Cc, hW, hist)                                                \
    do {                                                                           \
        const int ch0 = n0 >> 2;                                                   \
        _Pragma("unroll")                                                          \
        for (int it = 0; it < 16; it++) {                                          \
            const int idx = it * 256 + tid;                                        \
            const int bl = idx >> 5;                                               \
            const int jl = idx & 31;                                               \
            const int b = m0 + bl;                                                 \
            if (b >= Mt) continue;                                                 \
            const float4 v = *(const float4*)&cs[bl * 132 + 4 * jl];               \
            const int j = ch0 + jl;                                                \
            const float ig = 1.f / (1.f + __expf(-v.x));                           \
            const float fg = 1.f / (1.f + __expf(-v.y));                           \
            const float gg = tanhf(v.z);                                           \
            const float og = 1.f / (1.f + __expf(-v.w));                           \
            const size_t cidx = (size_t)b * HH + j;                                \
            const float cn = fg * (Cc)[cidx] + ig * gg;                            \
            const float hn = og * tanhf(cn);                                       \
            (Cc)[cidx] = cn;                                                       \
            const __half hh = __float2half(hn);                                    \
            g_Xh[(size_t)b * XS2 + (hW) + j] = hh;                                 \
            if (hist) (hist)[(size_t)b * HH + j] = hh;                             \
        }                                                                          \
    } while (0)

__global__ __launch_bounds__(256, 1)
void gemm_cell(const __half* __restrict__ A1, int ld1,
               const __half* __restrict__ A2, int ld2, int bnd,
               const __half* __restrict__ W, int ldw,
               const float* __restrict__ bias,
               float* __restrict__ Cc,
               int enc_t,                       // >=0: encoder step (Mt gate); -1: decoder
               int hW,
               __half* __restrict__ hist,
               int K) {
    extern __shared__ char smem[];
    const int m0 = (int)blockIdx.y * 128;
    const int n0 = (int)blockIdx.x * 128;
    const int Mt = (enc_t >= 0) ? g_Mt[enc_t] : BB;
    if (m0 >= Mt) return;

    GEMM_PROLOGUE();
    const size_t ld1B = (size_t)ld1 * 2, ld2B = (size_t)ld2 * 2;
    const size_t ldwB = (size_t)ldw * 2;
    const char* pA1 = (const char*)A1 + (size_t)(m0 + rowL) * ld1B;
    const char* pA2 = (const char*)A2 + (size_t)(m0 + rowL) * ld2B;
    const char* pW  = (const char*)W  + (size_t)(n0 + rowL) * ldwB;
    const int nch = K >> 6;

    GEMM_MAINLOOP4(LOADCHUNK_C);
    GEMM_ACC_TO_SMEM(bias + n0);
    CELL_EPILOGUE(Cc, hW, hist);
}

// fused encoder pair: part0 = encL1(t), part1 = encL0(t+1). grid (32,8).
__global__ __launch_bounds__(256, 1)
void enc_pair(int t) {
    extern __shared__ char smem[];
    const int part = (int)(blockIdx.y >> 2);
    const int m0 = (int)(blockIdx.y & 3) * 128;
    const int n0 = (int)blockIdx.x * 128;

    const int h0p = (t & 1) ? 1024 : 0;                   // H0(t)
    const int h1q = 2048 + (((t - 1) & 1) ? 1024 : 0);    // H1(t-1)
    const int h1p = 2048 + ((t & 1) ? 1024 : 0);          // H1(t)
    const int h0n = ((t + 1) & 1) ? 1024 : 0;             // H0(t+1)

    const __half *A1, *A2, *W;
    int ld1, ld2, bnd, ldw, K, hW, Mt;
    const float* bias;
    float* Cc;
    if (part == 0) {       // encL1(t): A=[h0(t) | h1(t-1)]
        A1 = g_Xh + h0p; ld1 = XS2;
        A2 = g_Xh + h1q; ld2 = XS2; bnd = 128;
        W = g_We1; ldw = K2048; K = K2048;
        bias = g_bias + GG; Cc = g_C1; hW = h1p; Mt = g_Mt[t];
    } else {               // encL0(t+1): A=[x(t+1) | h0(t)]
        A1 = g_Xall + (size_t)(t + 1) * BB * XALLW; ld1 = XALLW;
        A2 = g_Xh + h0p; ld2 = XS2; bnd = 17;
        W = g_We0; ldw = KE0; K = KE0;
        bias = g_bias; Cc = g_C0; hW = h0n; Mt = g_Mt[t + 1];
    }
    if (m0 >= Mt) return;

    GEMM_PROLOGUE();
    const size_t ld1B = (size_t)ld1 * 2, ld2B = (size_t)ld2 * 2;
    const size_t ldwB = (size_t)ldw * 2;
    const char* pA1 = (const char*)A1 + (size_t)(m0 + rowL) * ld1B;
    const char* pA2 = (const char*)A2 + (size_t)(m0 + rowL) * ld2B;
    const char* pW  = (const char*)W  + (size_t)(n0 + rowL) * ldwB;
    const int nch = K >> 6;

    GEMM_MAINLOOP4(LOADCHUNK_C);
    GEMM_ACC_TO_SMEM(bias + n0);
    CELL_EPILOGUE(Cc, hW, (__half*)nullptr);
}

// ===================== batched fc: out = H1hist @ fcW^T + fcb =====================
__global__ __launch_bounds__(256, 1)
void fc_batch(const float* __restrict__ fcb, float* __restrict__ out) {
    extern __shared__ char smem[];
    const int m0 = (int)blockIdx.x * 128;     // m = t*BB + b_sorted

    GEMM_PROLOGUE();
    const size_t ldaB = (size_t)HH * 2;
    const char* pA = (const char*)g_H1h + (size_t)(m0 + rowL) * ldaB + colL * 16;
    const char* pW = (const char*)g_fcWh + (size_t)rowL * ldaB + colL * 16;
    const int nch = HH >> 6;

#define LOADCHUNK_F(s, kc) do {                                                    \
    const uint32_t st_ = sb + (uint32_t)(s) * STAGE_B;                             \
    const size_t ko_ = (size_t)(kc) * 128;                                         \
    _Pragma("unroll")                                                              \
    for (int it = 0; it < 4; it++) {                                               \
        const uint32_t so_ = (uint32_t)(rowL + 32 * it) * 128 + swL;               \
        cpa16(st_ + so_, pA + ko_ + (size_t)(32 * it) * ldaB);                     \
        cpa16(st_ + TBYTES + so_, pW + ko_ + (size_t)(32 * it) * ldaB);            \
    }                                                                              \
    asm volatile("cp.async.commit_group;");                                        \
} while (0)

    LOADCHUNK_F(0, 0);
    LOADCHUNK_F(1, 1);
    for (int kc = 0; kc < nch; kc++) {
        if (kc + 1 < nch) { asm volatile("cp.async.wait_group 1;"); }
        else { asm volatile("cp.async.wait_group 0;"); }
        __syncthreads();
        if (kc + 2 < nch) { const int s_ = (kc + 2) % 3; LOADCHUNK_F(s_, kc + 2); }
        const uint32_t st = sb + (uint32_t)(kc % 3) * STAGE_B;
        GEMM_COMPUTE_CHUNK(st);
        __syncthreads();
    }

    GEMM_ACC_TO_SMEM(fcb);

#pragma unroll
    for (int it = 0; it < 16; it++) {
        const int idx = it * 256 + tid;
        const int bl = idx >> 5;
        const int jl = idx & 31;
        const int m = m0 + bl;
        const int bs = m & (BB - 1);
        const int tt = m >> 9;
        const int b = g_perm[bs];
        const float4 v = *(const float4*)&cs[bl * 132 + 4 * jl];
        *(float4*)&out[((size_t)b * STEPS + tt) * OUTN + 4 * jl] = v;
    }
}

// ===================== host =====================
extern "C" void kernel_launch(void* const* d_in, const int* in_sizes, int n_in,
                              void* d_out, int out_size) {
    const float* x     = (const float*)d_in[0];
    const int*   lens  = (const int*)  d_in[1];
    const float* eWih0 = (const float*)d_in[2];
    const float* eWhh0 = (const float*)d_in[3];
    const float* ebih0 = (const float*)d_in[4];
    const float* ebhh0 = (const float*)d_in[5];
    const float* eWih1 = (const float*)d_in[6];
    const float* eWhh1 = (const float*)d_in[7];
    const float* ebih1 = (const float*)d_in[8];
    const float* ebhh1 = (const float*)d_in[9];
    const float* dWih0 = (const float*)d_in[10];
    const float* dWhh0 = (const float*)d_in[11];
    const float* dbih0 = (const float*)d_in[12];
    const float* dbhh0 = (const float*)d_in[13];
    const float* dWih1 = (const float*)d_in[14];
    const float* dWhh1 = (const float*)d_in[15];
    const float* dbih1 = (const float*)d_in[16];
    const float* dbhh1 = (const float*)d_in[17];
    const float* fcW   = (const float*)d_in[18];
    const float* fcb   = (const float*)d_in[19];
    float* out = (float*)d_out;

    float *Bias, *C0, *C1;
    __half *Xh, *Xall, *We0, *We1, *Wd0, *Wd1, *H1h;
    cudaGetSymbolAddress((void**)&C0,   g_C0);
    cudaGetSymbolAddress((void**)&C1,   g_C1);
    cudaGetSymbolAddress((void**)&Bias, g_bias);
    cudaGetSymbolAddress((void**)&Xh,   g_Xh);
    cudaGetSymbolAddress((void**)&Xall, g_Xall);
    cudaGetSymbolAddress((void**)&We0,  g_We0);
    cudaGetSymbolAddress((void**)&We1,  g_We1);
    cudaGetSymbolAddress((void**)&Wd0,  g_Wd0);
    cudaGetSymbolAddress((void**)&Wd1,  g_Wd1);
    cudaGetSymbolAddress((void**)&H1h,  g_H1h);

    cudaFuncSetAttribute(gemm_cell, cudaFuncAttributeMaxDynamicSharedMemorySize, SMEM_G);
    cudaFuncSetAttribute(enc_pair,  cudaFuncAttributeMaxDynamicSharedMemorySize, SMEM_G);
    cudaFuncSetAttribute(fc_batch,  cudaFuncAttributeMaxDynamicSharedMemorySize, SMEM_F);

    // ---- setup ----
    setup_zero<<<2048, 256>>>();
    setup_sort<<<1, 128>>>(lens);
    setup_weights<<<8192, 256>>>(eWih0, eWhh0, eWih1, eWhh1, dWhh0, dWih1, dWhh1);
    setup_M0<<<dim3(128, 16), 256>>>(dWih0, fcW);
    setup_bias<<<16, 256>>>(ebih0, ebhh0, ebih1, ebhh1, dbih0, dbhh0, dbih1, dbhh1,
                            dWih0, fcb);
    setup_misc<<<4096, 256>>>(fcW, x);

    auto H0 = [](int t) { return (t & 1) ? 1024 : 0; };
    auto H1 = [](int t) { return (t & 1) ? 3072 : 2048; };

    const dim3 gg(32, 4), gp(32, 8), gb(256);

    // ---- encoder ----
    for (int t = 0; t < FUSE_T; t++) {
        gemm_cell<<<gg, gb, SMEM_G>>>(
            Xall + (size_t)t * BB * XALLW, XALLW, Xh + H0(t - 1), XS2, 17,
            We0, KE0, Bias + 0 * GG, C0, t, H0(t), nullptr, KE0);
        gemm_cell<<<gg, gb, SMEM_G>>>(
            Xh + H0(t), XS2, Xh + H1(t - 1), XS2, 128,
            We1, K2048, Bias + 1 * GG, C1, t, H1(t), nullptr, K2048);
    }
    // L0(FUSE_T) standalone, then fused pairs (L1(t), L0(t+1)), then final L1
    gemm_cell<<<gg, gb, SMEM_G>>>(
        Xall + (size_t)FUSE_T * BB * XALLW, XALLW, Xh + H0(FUSE_T - 1), XS2, 17,
        We0, KE0, Bias + 0 * GG, C0, FUSE_T, H0(FUSE_T), nullptr, KE0);
    for (int t = FUSE_T; t < TT - 1; t++)
        enc_pair<<<gp, gb, SMEM_G>>>(t);
    gemm_cell<<<gg, gb, SMEM_G>>>(
        Xh + H0(TT - 1), XS2, Xh + H1(TT - 2), XS2, 128,
        We1, K2048, Bias + 1 * GG, C1, TT - 1, H1(TT - 1), nullptr, K2048);

    // ---- fix-up final h0/h1 into odd slots for decoder t=0 ----
    fixup_h<<<(BB * HH + 255) / 256, 256>>>();

    // ---- decoder: 100 steps x 2 launches, fc folded / output batched ----
    gemm_cell<<<gg, gb, SMEM_G>>>(
        Xh + H0(-1), XS2, Xh + H0(-1), XS2, 128,
        Wd0, K2048, Bias + 2 * GG, C0, -1, H0(0), nullptr, 1024);
    gemm_cell<<<gg, gb, SMEM_G>>>(
        Xh + H0(0), XS2, Xh + H1(-1), XS2, 128,
        Wd1, K2048, Bias + 3 * GG, C1, -1, H1(0), H1h + 0, K2048);
    for (int t = 1; t < STEPS; t++) {
        gemm_cell<<<gg, gb, SMEM_G>>>(
            Xh + H0(t - 1), XS2, Xh + H1(t - 1), XS2, 128,
            Wd0, K2048, Bias + 4 * GG, C0, -1, H0(t), nullptr, K2048);
        gemm_cell<<<gg, gb, SMEM_G>>>(
            Xh + H0(t), XS2, Xh + H1(t - 1), XS2, 128,
            Wd1, K2048, Bias + 3 * GG, C1, -1, H1(t), H1h + (size_t)t * BB * HH, K2048);
    }

    // ---- one batched fc for all 100 steps (un-permutes on store) ----
    fc_batch<<<400, gb, SMEM_F>>>(fcb, out);
}

// round 17
// speedup vs baseline: 1.1298x; 1.0071x over previous
#include <cuda_runtime.h>
#include <cuda_fp16.h>
#include <cstdint>

#define BB 512
#define HH 1024
#define GG 4096
#define TT 82
#define DD 129
#define STEPS 100
#define OUTN 128
#define XS2 4096          // Xh row: h0_e(0) h0_o(1024) h1_e(2048) h1_o(3072)
#define XALLW 136
#define KE0 1216
#define K2048 2048
#define FUSE_T 42
#define THR 512           // 16 warps -> 4 warps/SMSP

// ===================== device scratch =====================
__device__ __half g_Xh [BB * XS2];
__device__ float  g_C0 [BB * HH];
__device__ float  g_C1 [BB * HH];
__device__ __half g_Xall[TT * BB * XALLW];
__device__ __half g_H1h [STEPS * BB * HH];
__device__ __half g_We0[GG * KE0];
__device__ __half g_We1[GG * K2048];
__device__ __half g_Wd0[GG * K2048];    // [Whh0 | M0=Wih0@fcW]
__device__ __half g_Wd1[GG * K2048];
__device__ __half g_fcWh[OUTN * HH];
__device__ float  g_bias[5 * GG];
__device__ int    g_perm[BB];
__device__ int    g_lenp[BB];
__device__ int    g_Mt[TT + 1];

__device__ __forceinline__ uint32_t smem_u32(const void* p) {
    uint32_t a;
    asm("{ .reg .u64 t; cvta.to.shared.u64 t, %1; cvt.u32.u64 %0, t; }" : "=r"(a) : "l"(p));
    return a;
}
__device__ __forceinline__ void cpa16(uint32_t s, const void* g) {
    asm volatile("cp.async.cg.shared.global [%0], [%1], 16;" :: "r"(s), "l"(g));
}
__device__ __forceinline__ void ldsm4(uint32_t (&d)[4], uint32_t addr) {
    asm volatile("ldmatrix.sync.aligned.m8n8.x4.shared.b16 {%0,%1,%2,%3}, [%4];"
                 : "=r"(d[0]), "=r"(d[1]), "=r"(d[2]), "=r"(d[3]) : "r"(addr));
}
__device__ __forceinline__ void mma16816(float (&d)[4], const uint32_t (&a)[4],
                                         uint32_t b0, uint32_t b1) {
    asm volatile("mma.sync.aligned.m16n8k16.row.col.f32.f16.f16.f32 "
                 "{%0,%1,%2,%3},{%4,%5,%6,%7},{%8,%9},{%0,%1,%2,%3};"
                 : "+f"(d[0]), "+f"(d[1]), "+f"(d[2]), "+f"(d[3])
                 : "r"(a[0]), "r"(a[1]), "r"(a[2]), "r"(a[3]), "r"(b0), "r"(b1));
}

// ===================== setup kernels =====================
__global__ void setup_zero() {
    const int n1 = BB * XS2 / 2;
    const int n2 = BB * HH;
    const int n3 = BB * HH;
    const int total = n1 + n2 + n3;
    for (int i = blockIdx.x * blockDim.x + threadIdx.x; i < total; i += gridDim.x * blockDim.x) {
        if (i < n1) ((uint32_t*)g_Xh)[i] = 0u;
        else if (i < n1 + n2) g_C0[i - n1] = 0.f;
        else g_C1[i - n1 - n2] = 0.f;
    }
}

__global__ void setup_sort(const int* __restrict__ lengths) {
    __shared__ int hist[TT + 2];
    __shared__ int off[TT + 2];
    const int tid = threadIdx.x;
    if (tid < TT + 2) hist[tid] = 0;
    __syncthreads();
    if (tid == 0) {
        for (int b = 0; b < BB; b++) hist[lengths[b]]++;
        int acc = 0;
        for (int L = TT; L >= 1; L--) { off[L] = acc; acc += hist[L]; }
        for (int b = 0; b < BB; b++) {
            const int L = lengths[b];
            const int pos = off[L]++;
            g_perm[pos] = b;
            g_lenp[pos] = L;
        }
        for (int t = 0; t < TT; t++) {
            int c = 0;
            for (int L = t + 1; L <= TT; L++) c += hist[L];
            g_Mt[t] = c;
        }
        g_Mt[TT] = 0;
    }
}

__global__ void setup_weights(const float* __restrict__ eWih0, const float* __restrict__ eWhh0,
                              const float* __restrict__ eWih1, const float* __restrict__ eWhh1,
                              const float* __restrict__ dWhh0,
                              const float* __restrict__ dWih1, const float* __restrict__ dWhh1) {
    const long S0 = (long)GG * KE0;
    const long S1 = (long)GG * K2048;
    const long S2 = (long)GG * K2048;
    const long S3 = (long)GG * 1024;
    const long total = S0 + S1 + S2 + S3;
    for (long i = blockIdx.x * (long)blockDim.x + threadIdx.x; i < total;
         i += (long)gridDim.x * blockDim.x) {
        if (i < S0) {
            int nd = (int)(i / KE0), k = (int)(i % KE0);
            int n = (nd & 3) * HH + (nd >> 2);
            float v = 0.f;
            if (k < 129) v = eWih0[(size_t)n * 129 + k];
            else if (k >= 136 && k < 1160) v = eWhh0[(size_t)n * 1024 + (k - 136)];
            g_We0[i] = __float2half(v);
        } else if (i < S0 + S1) {
            long j = i - S0;
            int nd = (int)(j / K2048), k = (int)(j % K2048);
            int n = (nd & 3) * HH + (nd >> 2);
            float v = (k < 1024) ? eWih1[(size_t)n * 1024 + k]
                                 : eWhh1[(size_t)n * 1024 + (k - 1024)];
            g_We1[j] = __float2half(v);
        } else if (i < S0 + S1 + S2) {
            long j = i - S0 - S1;
            int nd = (int)(j / K2048), k = (int)(j % K2048);
            int n = (nd & 3) * HH + (nd >> 2);
            float v = (k < 1024) ? dWih1[(size_t)n * 1024 + k]
                                 : dWhh1[(size_t)n * 1024 + (k - 1024)];
            g_Wd1[j] = __float2half(v);
        } else {
            long j = i - S0 - S1 - S2;
            int nd = (int)(j / 1024), k = (int)(j % 1024);
            int n = (nd & 3) * HH + (nd >> 2);
            g_Wd0[(size_t)nd * K2048 + k] = __float2half(dWhh0[(size_t)n * 1024 + k]);
        }
    }
}

__global__ void setup_M0(const float* __restrict__ dWih0, const float* __restrict__ fcW) {
    __shared__ float sW[32][128];
    __shared__ float sF[128][64];
    const int nd0 = blockIdx.x * 32;
    const int k0  = blockIdx.y * 64;
    const int tid = threadIdx.x;
    for (int i = tid; i < 32 * 128; i += 256) {
        int r = i >> 7, o = i & 127;
        int nd = nd0 + r, n = (nd & 3) * HH + (nd >> 2);
        sW[r][o] = dWih0[(size_t)n * 128 + o];
    }
    for (int i = tid; i < 128 * 64; i += 256) {
        int o = i >> 6, kk = i & 63;
        sF[o][kk] = fcW[(size_t)o * HH + k0 + kk];
    }
    __syncthreads();
    for (int i = tid; i < 32 * 64; i += 256) {
        int r = i >> 6, kk = i & 63;
        float acc = 0.f;
#pragma unroll 16
        for (int o = 0; o < 128; o++) acc += sW[r][o] * sF[o][kk];
        g_Wd0[(size_t)(nd0 + r) * K2048 + 1024 + k0 + kk] = __float2half(acc);
    }
}

__global__ void setup_bias(const float* eb0a, const float* eb0b,
                           const float* eb1a, const float* eb1b,
                           const float* db0a, const float* db0b,
                           const float* db1a, const float* db1b,
                           const float* __restrict__ dWih0, const float* __restrict__ fcb) {
    int nd = blockIdx.x * blockDim.x + threadIdx.x;
    if (nd >= GG) return;
    int n = (nd & 3) * HH + (nd >> 2);
    g_bias[0 * GG + nd] = eb0a[n] + eb0b[n];
    g_bias[1 * GG + nd] = eb1a[n] + eb1b[n];
    float d0 = db0a[n] + db0b[n];
    g_bias[2 * GG + nd] = d0;
    g_bias[3 * GG + nd] = db1a[n] + db1b[n];
    float acc = 0.f;
#pragma unroll 16
    for (int o = 0; o < 128; o++) acc += dWih0[(size_t)n * 128 + o] * fcb[o];
    g_bias[4 * GG + nd] = d0 + acc;
}

__global__ void setup_misc(const float* __restrict__ fcW, const float* __restrict__ x) {
    const int t1 = OUTN * HH;
    const int t2 = TT * BB * XALLW;
    for (int i = blockIdx.x * blockDim.x + threadIdx.x; i < t1 + t2;
         i += gridDim.x * blockDim.x) {
        if (i < t1) {
            g_fcWh[i] = __float2half(fcW[i]);
        } else {
            int j = i - t1;
            int tt = j / (BB * XALLW);
            int r = j % (BB * XALLW);
            int bs = r / XALLW, k = r % XALLW;
            const int b = g_perm[bs];
            float v = (k < DD) ? x[(size_t)b * (TT * DD) + tt * DD + k] : 0.f;
            g_Xall[j] = __float2half(v);
        }
    }
}

__global__ void fixup_h() {
    const int idx = blockIdx.x * blockDim.x + threadIdx.x;
    if (idx >= BB * HH) return;
    const int b = idx >> 10, j = idx & 1023;
    const int p = (g_lenp[b] - 1) & 1;
    const size_t row = (size_t)b * XS2;
    const __half h0f = g_Xh[row + p * 1024 + j];
    const __half h1f = g_Xh[row + 2048 + p * 1024 + j];
    g_Xh[row + 1024 + j] = h0f;
    g_Xh[row + 3072 + j] = h1f;
}

// ===================== fused GEMM + LSTM cell (512 threads, warp tile 32x32) =====================
#define TBYTES 16384
#define STAGE_B (2 * TBYTES)      // 32 KB
#define SMEM_G  (4 * STAGE_B)     // 128 KB: 4-stage
#define SMEM_F  (3 * STAGE_B)     // 96 KB: fc_batch 3-stage

// warp grid 4x4, warp tile 32x32; loader: rowL 0..63, two row-halves per tile
#define GEMM_PROLOGUE()                                                            \
    const uint32_t sb = smem_u32(smem);                                            \
    const int tid = threadIdx.x;                                                   \
    const int l = tid & 31;                                                        \
    const int wid = tid >> 5;                                                      \
    const int warp_m = wid >> 2;          /* 0..3 */                               \
    const int warp_n = wid & 3;           /* 0..3 */                               \
    const int rowL = tid >> 3;            /* 0..63 */                              \
    const int colL = tid & 7;                                                      \
    const uint32_t swL = (uint32_t)(colL ^ (rowL & 7)) * 16;                       \
    uint32_t arow[2], ar7[2];                                                      \
    _Pragma("unroll")                                                              \
    for (int wm = 0; wm < 2; wm++) {                                               \
        const uint32_t r = warp_m * 32 + wm * 16 + (l & 15);                       \
        arow[wm] = r * 128; ar7[wm] = r & 7;                                       \
    }                                                                              \
    uint32_t brow[2], br7[2];                                                      \
    _Pragma("unroll")                                                              \
    for (int p = 0; p < 2; p++) {                                                  \
        const uint32_t r = warp_n * 32 + p * 16 + ((l >> 4) << 3) + (l & 7);       \
        brow[p] = r * 128; br7[p] = r & 7;                                         \
    }                                                                              \
    const uint32_t acsel = (uint32_t)(l >> 4);                                     \
    const uint32_t bcsel = (uint32_t)((l >> 3) & 1);                               \
    float acc[2][4][4];                                                            \
    _Pragma("unroll")                                                              \
    for (int i = 0; i < 2; i++)                                                    \
        _Pragma("unroll")                                                          \
        for (int j = 0; j < 4; j++)                                                \
            _Pragma("unroll")                                                      \
            for (int q = 0; q < 4; q++) acc[i][j][q] = 0.f;

#define GEMM_COMPUTE_CHUNK(st)                                                     \
    _Pragma("unroll")                                                              \
    for (int ks = 0; ks < 4; ks++) {                                               \
        uint32_t AH[2][4], BH[2][4];                                               \
        _Pragma("unroll")                                                          \
        for (int wm = 0; wm < 2; wm++) {                                           \
            const uint32_t c = (uint32_t)(2 * ks) + acsel;                         \
            ldsm4(AH[wm], (st) + arow[wm] + ((c ^ ar7[wm]) << 4));                 \
        }                                                                          \
        _Pragma("unroll")                                                          \
        for (int p = 0; p < 2; p++) {                                              \
            const uint32_t c = (uint32_t)(2 * ks) + bcsel;                         \
            ldsm4(BH[p], (st) + TBYTES + brow[p] + ((c ^ br7[p]) << 4));           \
        }                                                                          \
        _Pragma("unroll")                                                          \
        for (int wm = 0; wm < 2; wm++) {                                           \
            _Pragma("unroll")                                                      \
            for (int wn = 0; wn < 4; wn++) {                                       \
                const int p = wn >> 1, h = (wn & 1) << 1;                          \
                mma16816(acc[wm][wn], AH[wm], BH[p][h], BH[p][h + 1]);             \
            }                                                                      \
        }                                                                          \
    }

#define GEMM_MAINLOOP4(LOADCHUNK)                                                  \
    LOADCHUNK(0, 0);                                                               \
    LOADCHUNK(1, 1);                                                               \
    LOADCHUNK(2, 2);                                                               \
    for (int kc = 0; kc < nch; kc++) {                                             \
        if (kc + 2 < nch) { asm volatile("cp.async.wait_group 2;"); }              \
        else if (kc + 1 < nch) { asm volatile("cp.async.wait_group 1;"); }         \
        else { asm volatile("cp.async.wait_group 0;"); }                           \
        __syncthreads();                                                           \
        if (kc + 3 < nch) LOADCHUNK((kc + 3) & 3, kc + 3);                         \
        const uint32_t st = sb + (uint32_t)(kc & 3) * STAGE_B;                     \
        GEMM_COMPUTE_CHUNK(st);                                                    \
    }                                                                              \
    __syncthreads();

#define GEMM_ACC_TO_SMEM(biasptr)                                                  \
    float* cs = (float*)smem;                                                      \
    _Pragma("unroll")                                                              \
    for (int wn = 0; wn < 4; wn++) {                                               \
        const int cl = warp_n * 32 + wn * 8 + (l & 3) * 2;                         \
        const float2 bv = *(const float2*)((biasptr) + cl);                        \
        _Pragma("unroll")                                                          \
        for (int wm = 0; wm < 2; wm++) {                                           \
            const int rl = warp_m * 32 + wm * 16 + (l >> 2);                       \
            cs[rl * 132 + cl]           = acc[wm][wn][0] + bv.x;                   \
            cs[rl * 132 + cl + 1]       = acc[wm][wn][1] + bv.y;                   \
            cs[(rl + 8) * 132 + cl]     = acc[wm][wn][2] + bv.x;                   \
            cs[(rl + 8) * 132 + cl + 1] = acc[wm][wn][3] + bv.y;                   \
        }                                                                          \
    }                                                                              \
    __syncthreads();

// two-source A + W loader (512 threads: 2 row-halves per tile)
#define LOADCHUNK_C(s, kc) do {                                                    \
    const uint32_t st_ = sb + (uint32_t)(s) * STAGE_B;                             \
    const int gcol_ = (kc) * 8 + colL;                                             \
    const char* ap_; size_t astep_;                                                \
    if (gcol_ < bnd) { ap_ = pA1 + (size_t)gcol_ * 16; astep_ = ld1B * 64; }       \
    else { ap_ = pA2 + (size_t)(gcol_ - bnd) * 16; astep_ = ld2B * 64; }           \
    const char* wp_ = pW + (size_t)gcol_ * 16;                                     \
    _Pragma("unroll")                                                              \
    for (int it = 0; it < 2; it++) {                                               \
        const uint32_t so_ = (uint32_t)(rowL + 64 * it) * 128 + swL;               \
        cpa16(st_ + so_, ap_ + (size_t)it * astep_);                               \
        cpa16(st_ + TBYTES + so_, wp_ + (size_t)(64 * it) * ldwB);                 \
    }                                                                              \
    asm volatile("cp.async.commit_group;");                                        \
} while (0)

#define CELL_EPILOGUE(Cc, hW, hist)                                                \
    do {                                                                           \
        const int ch0 = n0 >> 2;                                                   \
        _Pragma("unroll")                                                          \
        for (int it = 0; it < 8; it++) {                                           \
            const int idx = it * THR + tid;                                        \
            const int bl = idx >> 5;                                               \
            const int jl = idx & 31;                                               \
            const int b = m0 + bl;                                                 \
            if (b >= Mt) continue;                                                 \
            const float4 v = *(const float4*)&cs[bl * 132 + 4 * jl];               \
            const int j = ch0 + jl;                                                \
            const float ig = 1.f / (1.f + __expf(-v.x));                           \
            const float fg = 1.f / (1.f + __expf(-v.y));                           \
            const float gg = tanhf(v.z);                                           \
            const float og = 1.f / (1.f + __expf(-v.w));                           \
            const size_t cidx = (size_t)b * HH + j;                                \
            const float cn = fg * (Cc)[cidx] + ig * gg;                            \
            const float hn = og * tanhf(cn);                                       \
            (Cc)[cidx] = cn;                                                       \
            const __half hh = __float2half(hn);                                    \
            g_Xh[(size_t)b * XS2 + (hW) + j] = hh;                                 \
            if (hist) (hist)[(size_t)b * HH + j] = hh;                             \
        }                                                                          \
    } while (0)

__global__ __launch_bounds__(THR, 1)
void gemm_cell(const __half* __restrict__ A1, int ld1,
               const __half* __restrict__ A2, int ld2, int bnd,
               const __half* __restrict__ W, int ldw,
               const float* __restrict__ bias,
               float* __restrict__ Cc,
               int enc_t, int hW,
               __half* __restrict__ hist,
               int K) {
    extern __shared__ char smem[];
    const int m0 = (int)blockIdx.y * 128;
    const int n0 = (int)blockIdx.x * 128;
    const int Mt = (enc_t >= 0) ? g_Mt[enc_t] : BB;
    if (m0 >= Mt) return;

    GEMM_PROLOGUE();
    const size_t ld1B = (size_t)ld1 * 2, ld2B = (size_t)ld2 * 2;
    const size_t ldwB = (size_t)ldw * 2;
    const char* pA1 = (const char*)A1 + (size_t)(m0 + rowL) * ld1B;
    const char* pA2 = (const char*)A2 + (size_t)(m0 + rowL) * ld2B;
    const char* pW  = (const char*)W  + (size_t)(n0 + rowL) * ldwB;
    const int nch = K >> 6;

    GEMM_MAINLOOP4(LOADCHUNK_C);
    GEMM_ACC_TO_SMEM(bias + n0);
    CELL_EPILOGUE(Cc, hW, hist);
}

// fused encoder pair: part0 = encL1(t), part1 = encL0(t+1). grid (32,8).
__global__ __launch_bounds__(THR, 1)
void enc_pair(int t) {
    extern __shared__ char smem[];
    const int part = (int)(blockIdx.y >> 2);
    const int m0 = (int)(blockIdx.y & 3) * 128;
    const int n0 = (int)blockIdx.x * 128;

    const int h0p = (t & 1) ? 1024 : 0;
    const int h1q = 2048 + (((t - 1) & 1) ? 1024 : 0);
    const int h1p = 2048 + ((t & 1) ? 1024 : 0);
    const int h0n = ((t + 1) & 1) ? 1024 : 0;

    const __half *A1, *A2, *W;
    int ld1, ld2, bnd, ldw, K, hW, Mt;
    const float* bias;
    float* Cc;
    if (part == 0) {
        A1 = g_Xh + h0p; ld1 = XS2;
        A2 = g_Xh + h1q; ld2 = XS2; bnd = 128;
        W = g_We1; ldw = K2048; K = K2048;
        bias = g_bias + GG; Cc = g_C1; hW = h1p; Mt = g_Mt[t];
    } else {
        A1 = g_Xall + (size_t)(t + 1) * BB * XALLW; ld1 = XALLW;
        A2 = g_Xh + h0p; ld2 = XS2; bnd = 17;
        W = g_We0; ldw = KE0; K = KE0;
        bias = g_bias; Cc = g_C0; hW = h0n; Mt = g_Mt[t + 1];
    }
    if (m0 >= Mt) return;

    GEMM_PROLOGUE();
    const size_t ld1B = (size_t)ld1 * 2, ld2B = (size_t)ld2 * 2;
    const size_t ldwB = (size_t)ldw * 2;
    const char* pA1 = (const char*)A1 + (size_t)(m0 + rowL) * ld1B;
    const char* pA2 = (const char*)A2 + (size_t)(m0 + rowL) * ld2B;
    const char* pW  = (const char*)W  + (size_t)(n0 + rowL) * ldwB;
    const int nch = K >> 6;

    GEMM_MAINLOOP4(LOADCHUNK_C);
    GEMM_ACC_TO_SMEM(bias + n0);
    CELL_EPILOGUE(Cc, hW, (__half*)nullptr);
}

// ===================== batched fc =====================
__global__ __launch_bounds__(THR, 1)
void fc_batch(const float* __restrict__ fcb, float* __restrict__ out) {
    extern __shared__ char smem[];
    const int m0 = (int)blockIdx.x * 128;

    GEMM_PROLOGUE();
    const size_t ldaB = (size_t)HH * 2;
    const char* pA = (const char*)g_H1h + (size_t)(m0 + rowL) * ldaB + colL * 16;
    const char* pW = (const char*)g_fcWh + (size_t)rowL * ldaB + colL * 16;
    const int nch = HH >> 6;

#define LOADCHUNK_F(s, kc) do {                                                    \
    const uint32_t st_ = sb + (uint32_t)(s) * STAGE_B;                             \
    const size_t ko_ = (size_t)(kc) * 128;                                         \
    _Pragma("unroll")                                                              \
    for (int it = 0; it < 2; it++) {                                               \
        const uint32_t so_ = (uint32_t)(rowL + 64 * it) * 128 + swL;               \
        cpa16(st_ + so_, pA + ko_ + (size_t)(64 * it) * ldaB);                     \
        cpa16(st_ + TBYTES + so_, pW + ko_ + (size_t)(64 * it) * ldaB);            \
    }                                                                              \
    asm volatile("cp.async.commit_group;");                                        \
} while (0)

    LOADCHUNK_F(0, 0);
    LOADCHUNK_F(1, 1);
    for (int kc = 0; kc < nch; kc++) {
        if (kc + 1 < nch) { asm volatile("cp.async.wait_group 1;"); }
        else { asm volatile("cp.async.wait_group 0;"); }
        __syncthreads();
        if (kc + 2 < nch) { const int s_ = (kc + 2) % 3; LOADCHUNK_F(s_, kc + 2); }
        const uint32_t st = sb + (uint32_t)(kc % 3) * STAGE_B;
        GEMM_COMPUTE_CHUNK(st);
        __syncthreads();
    }

    GEMM_ACC_TO_SMEM(fcb);

#pragma unroll
    for (int it = 0; it < 8; it++) {
        const int idx = it * THR + tid;
        const int bl = idx >> 5;
        const int jl = idx & 31;
        const int m = m0 + bl;
        const int bs = m & (BB - 1);
        const int tt = m >> 9;
        const int b = g_perm[bs];
        const float4 v = *(const float4*)&cs[bl * 132 + 4 * jl];
        *(float4*)&out[((size_t)b * STEPS + tt) * OUTN + 4 * jl] = v;
    }
}

// ===================== host =====================
extern "C" void kernel_launch(void* const* d_in, const int* in_sizes, int n_in,
                              void* d_out, int out_size) {
    const float* x     = (const float*)d_in[0];
    const int*   lens  = (const int*)  d_in[1];
    const float* eWih0 = (const float*)d_in[2];
    const float* eWhh0 = (const float*)d_in[3];
    const float* ebih0 = (const float*)d_in[4];
    const float* ebhh0 = (const float*)d_in[5];
    const float* eWih1 = (const float*)d_in[6];
    const float* eWhh1 = (const float*)d_in[7];
    const float* ebih1 = (const float*)d_in[8];
    const float* ebhh1 = (const float*)d_in[9];
    const float* dWih0 = (const float*)d_in[10];
    const float* dWhh0 = (const float*)d_in[11];
    const float* dbih0 = (const float*)d_in[12];
    const float* dbhh0 = (const float*)d_in[13];
    const float* dWih1 = (const float*)d_in[14];
    const float* dWhh1 = (const float*)d_in[15];
    const float* dbih1 = (const float*)d_in[16];
    const float* dbhh1 = (const float*)d_in[17];
    const float* fcW   = (const float*)d_in[18];
    const float* fcb   = (const float*)d_in[19];
    float* out = (float*)d_out;

    float *Bias, *C0, *C1;
    __half *Xh, *Xall, *We0, *We1, *Wd0, *Wd1, *H1h;
    cudaGetSymbolAddress((void**)&C0,   g_C0);
    cudaGetSymbolAddress((void**)&C1,   g_C1);
    cudaGetSymbolAddress((void**)&Bias, g_bias);
    cudaGetSymbolAddress((void**)&Xh,   g_Xh);
    cudaGetSymbolAddress((void**)&Xall, g_Xall);
    cudaGetSymbolAddress((void**)&We0,  g_We0);
    cudaGetSymbolAddress((void**)&We1,  g_We1);
    cudaGetSymbolAddress((void**)&Wd0,  g_Wd0);
    cudaGetSymbolAddress((void**)&Wd1,  g_Wd1);
    cudaGetSymbolAddress((void**)&H1h,  g_H1h);

    cudaFuncSetAttribute(gemm_cell, cudaFuncAttributeMaxDynamicSharedMemorySize, SMEM_G);
    cudaFuncSetAttribute(enc_pair,  cudaFuncAttributeMaxDynamicSharedMemorySize, SMEM_G);
    cudaFuncSetAttribute(fc_batch,  cudaFuncAttributeMaxDynamicSharedMemorySize, SMEM_F);

    // ---- setup ----
    setup_zero<<<2048, 256>>>();
    setup_sort<<<1, 128>>>(lens);
    setup_weights<<<8192, 256>>>(eWih0, eWhh0, eWih1, eWhh1, dWhh0, dWih1, dWhh1);
    setup_M0<<<dim3(128, 16), 256>>>(dWih0, fcW);
    setup_bias<<<16, 256>>>(ebih0, ebhh0, ebih1, ebhh1, dbih0, dbhh0, dbih1, dbhh1,
                            dWih0, fcb);
    setup_misc<<<4096, 256>>>(fcW, x);

    auto H0 = [](int t) { return (t & 1) ? 1024 : 0; };
    auto H1 = [](int t) { return (t & 1) ? 3072 : 2048; };

    const dim3 gg(32, 4), gp(32, 8), gb(THR);

    // ---- encoder ----
    for (int t = 0; t < FUSE_T; t++) {
        gemm_cell<<<gg, gb, SMEM_G>>>(
            Xall + (size_t)t * BB * XALLW, XALLW, Xh + H0(t - 1), XS2, 17,
            We0, KE0, Bias + 0 * GG, C0, t, H0(t), nullptr, KE0);
        gemm_cell<<<gg, gb, SMEM_G>>>(
            Xh + H0(t), XS2, Xh + H1(t - 1), XS2, 128,
            We1, K2048, Bias + 1 * GG, C1, t, H1(t), nullptr, K2048);
    }
    gemm_cell<<<gg, gb, SMEM_G>>>(
        Xall + (size_t)FUSE_T * BB * XALLW, XALLW, Xh + H0(FUSE_T - 1), XS2, 17,
        We0, KE0, Bias + 0 * GG, C0, FUSE_T, H0(FUSE_T), nullptr, KE0);
    for (int t = FUSE_T; t < TT - 1; t++)
        enc_pair<<<gp, gb, SMEM_G>>>(t);
    gemm_cell<<<gg, gb, SMEM_G>>>(
        Xh + H0(TT - 1), XS2, Xh + H1(TT - 2), XS2, 128,
        We1, K2048, Bias + 1 * GG, C1, TT - 1, H1(TT - 1), nullptr, K2048);

    // ---- fix-up final h0/h1 into odd slots for decoder t=0 ----
    fixup_h<<<(BB * HH + 255) / 256, 256>>>();

    // ---- decoder ----
    gemm_cell<<<gg, gb, SMEM_G>>>(
        Xh + H0(-1), XS2, Xh + H0(-1), XS2, 128,
        Wd0, K2048, Bias + 2 * GG, C0, -1, H0(0), nullptr, 1024);
    gemm_cell<<<gg, gb, SMEM_G>>>(
        Xh + H0(0), XS2, Xh + H1(-1), XS2, 128,
        Wd1, K2048, Bias + 3 * GG, C1, -1, H1(0), H1h + 0, K2048);
    for (int t = 1; t < STEPS; t++) {
        gemm_cell<<<gg, gb, SMEM_G>>>(
            Xh + H0(t - 1), XS2, Xh + H1(t - 1), XS2, 128,
            Wd0, K2048, Bias + 4 * GG, C0, -1, H0(t), nullptr, K2048);
        gemm_cell<<<gg, gb, SMEM_G>>>(
            Xh + H0(t), XS2, Xh + H1(t - 1), XS2, 128,
            Wd1, K2048, Bias + 3 * GG, C1, -1, H1(t), H1h + (size_t)t * BB * HH, K2048);
    }

    // ---- one batched fc ----
    fc_batch<<<400, gb, SMEM_F>>>(fcb, out);
}